// round 1
// baseline (speedup 1.0000x reference)
#include <cuda_runtime.h>
#include <cuda_bf16.h>

// Problem constants
#define BATCH 2
#define SEQ 2048
#define HIDDEN 2048
#define NHEADS 32
#define NKV 8
#define HDIM 64
#define KVDIM 512
#define MROWS (BATCH * SEQ)   // 4096

// Scratch (allocation-free rule: __device__ globals)
__device__ float g_q[MROWS * HIDDEN];  // [B*S, H*D]
__device__ float g_k[MROWS * KVDIM];   // [B*S, Hk*D]
__device__ float g_v[MROWS * KVDIM];
__device__ float g_o[MROWS * HIDDEN];  // attention output, pre O-proj

// ---------------------------------------------------------------------------
// Generic GEMM: C[M,N] = A[M,K] @ W[N,K]^T + bias[N]
// Both A and W are K-contiguous => coalesced float4 loads along K.
// BM=BN=64, BK=16, 256 threads, 4x4 register tile per thread.
// ---------------------------------------------------------------------------
#define BM 64
#define BN 64
#define BK 16

__global__ __launch_bounds__(256) void gemm_bias_kernel(
    const float* __restrict__ A, const float* __restrict__ W,
    const float* __restrict__ bias, float* __restrict__ C,
    int M, int N, int K)
{
    __shared__ float As[BK][BM];  // transposed: [k][m]
    __shared__ float Ws[BK][BN];  // transposed: [k][n]

    const int tid = threadIdx.x;
    const int tm = tid >> 4;      // 0..15
    const int tn = tid & 15;      // 0..15
    const int bm = blockIdx.y * BM;
    const int bn = blockIdx.x * BN;

    const int lr = tid >> 2;          // 0..63 (tile row for loading)
    const int lk = (tid & 3) << 2;    // 0,4,8,12

    const float* Aptr = A + (size_t)(bm + lr) * K + lk;
    const float* Wptr = W + (size_t)(bn + lr) * K + lk;

    float acc[4][4] = {};

    for (int k0 = 0; k0 < K; k0 += BK) {
        float4 a4 = *(const float4*)(Aptr + k0);
        float4 w4 = *(const float4*)(Wptr + k0);
        As[lk + 0][lr] = a4.x; As[lk + 1][lr] = a4.y;
        As[lk + 2][lr] = a4.z; As[lk + 3][lr] = a4.w;
        Ws[lk + 0][lr] = w4.x; Ws[lk + 1][lr] = w4.y;
        Ws[lk + 2][lr] = w4.z; Ws[lk + 3][lr] = w4.w;
        __syncthreads();

#pragma unroll
        for (int kk = 0; kk < BK; kk++) {
            float4 av = *(const float4*)&As[kk][tm << 2];
            float4 wv = *(const float4*)&Ws[kk][tn << 2];
            acc[0][0] += av.x * wv.x; acc[0][1] += av.x * wv.y;
            acc[0][2] += av.x * wv.z; acc[0][3] += av.x * wv.w;
            acc[1][0] += av.y * wv.x; acc[1][1] += av.y * wv.y;
            acc[1][2] += av.y * wv.z; acc[1][3] += av.y * wv.w;
            acc[2][0] += av.z * wv.x; acc[2][1] += av.z * wv.y;
            acc[2][2] += av.z * wv.z; acc[2][3] += av.z * wv.w;
            acc[3][0] += av.w * wv.x; acc[3][1] += av.w * wv.y;
            acc[3][2] += av.w * wv.z; acc[3][3] += av.w * wv.w;
        }
        __syncthreads();
    }

    float4 b4 = *(const float4*)(bias + bn + (tn << 2));
#pragma unroll
    for (int i = 0; i < 4; i++) {
        int row = bm + (tm << 2) + i;
        float4 o;
        o.x = acc[i][0] + b4.x;
        o.y = acc[i][1] + b4.y;
        o.z = acc[i][2] + b4.z;
        o.w = acc[i][3] + b4.w;
        *(float4*)(C + (size_t)row * N + bn + (tn << 2)) = o;
    }
}

// ---------------------------------------------------------------------------
// Flash attention (fp32). One CTA = (b, h, 64-query tile). 256 threads.
// Q layout: [B*S, H*D]; K/V layout: [B*S, Hk*D].
// smem: Qs[64][64] (q-major), KP[64][64] (K transposed [d][k], reused as P[q][k]),
//       Vs[64][64] (k-major). 48KB total.
// ---------------------------------------------------------------------------
__global__ __launch_bounds__(256) void attn_kernel(
    const float* __restrict__ Q, const float* __restrict__ Kg,
    const float* __restrict__ Vg, float* __restrict__ O)
{
    __shared__ float Qs[64][64];
    __shared__ float KP[64][64];
    __shared__ float Vs[64][64];

    const int tid = threadIdx.x;
    const int qb = blockIdx.x;     // 0..31
    const int h  = blockIdx.y;     // 0..31
    const int b  = blockIdx.z;     // 0..1
    const int kvh = h >> 2;
    const int tq = tid >> 4;       // 0..15
    const int tk = tid & 15;       // 0..15
    const float scale = 0.125f;    // 1/sqrt(64)

    // Load Q tile (pre-scaled)
    for (int i = tid; i < 64 * 16; i += 256) {
        int r = i >> 4;
        int c = (i & 15) << 2;
        float4 v = *(const float4*)(Q + (size_t)(b * SEQ + qb * 64 + r) * HIDDEN + h * HDIM + c);
        float4 s;
        s.x = v.x * scale; s.y = v.y * scale; s.z = v.z * scale; s.w = v.w * scale;
        *(float4*)&Qs[r][c] = s;
    }

    float o[4][4] = {};
    float m[4] = {-1e30f, -1e30f, -1e30f, -1e30f};
    float l[4] = {};

    for (int jb = 0; jb < SEQ / 64; jb++) {
        __syncthreads();  // previous-iteration reads of KP/Vs done (also covers Q load)

        // Load K tile transposed into KP[d][k]; V tile into Vs[k][d]
        for (int i = tid; i < 64 * 16; i += 256) {
            int r = i >> 4;                 // key row within tile
            int c = (i & 15) << 2;          // d0
            size_t base = (size_t)(b * SEQ + jb * 64 + r) * KVDIM + kvh * HDIM + c;
            float4 kv = *(const float4*)(Kg + base);
            KP[c + 0][r] = kv.x; KP[c + 1][r] = kv.y;
            KP[c + 2][r] = kv.z; KP[c + 3][r] = kv.w;
            float4 vv = *(const float4*)(Vg + base);
            *(float4*)&Vs[r][c] = vv;
        }
        __syncthreads();

        // Scores: s[4q][4k] = Qs[q][:] . K[k][:]
        float s[4][4] = {};
#pragma unroll 16
        for (int d = 0; d < 64; d++) {
            float a0 = Qs[(tq << 2) + 0][d];
            float a1 = Qs[(tq << 2) + 1][d];
            float a2 = Qs[(tq << 2) + 2][d];
            float a3 = Qs[(tq << 2) + 3][d];
            float4 kk = *(const float4*)&KP[d][tk << 2];
            s[0][0] += a0 * kk.x; s[0][1] += a0 * kk.y; s[0][2] += a0 * kk.z; s[0][3] += a0 * kk.w;
            s[1][0] += a1 * kk.x; s[1][1] += a1 * kk.y; s[1][2] += a1 * kk.z; s[1][3] += a1 * kk.w;
            s[2][0] += a2 * kk.x; s[2][1] += a2 * kk.y; s[2][2] += a2 * kk.z; s[2][3] += a2 * kk.w;
            s[3][0] += a3 * kk.x; s[3][1] += a3 * kk.y; s[3][2] += a3 * kk.z; s[3][3] += a3 * kk.w;
        }

        // Online softmax (row groups = 16 tk lanes share a q row)
        float sf[4];
#pragma unroll
        for (int i = 0; i < 4; i++) {
            float mx = fmaxf(fmaxf(s[i][0], s[i][1]), fmaxf(s[i][2], s[i][3]));
#pragma unroll
            for (int off = 8; off > 0; off >>= 1)
                mx = fmaxf(mx, __shfl_xor_sync(0xffffffffu, mx, off));
            float mnew = fmaxf(m[i], mx);
            sf[i] = __expf(m[i] - mnew);
            float rs = 0.f;
#pragma unroll
            for (int j = 0; j < 4; j++) {
                s[i][j] = __expf(s[i][j] - mnew);
                rs += s[i][j];
            }
#pragma unroll
            for (int off = 8; off > 0; off >>= 1)
                rs += __shfl_xor_sync(0xffffffffu, rs, off);
            l[i] = l[i] * sf[i] + rs;
            m[i] = mnew;
        }

        __syncthreads();  // everyone done reading KP as K-transposed

        // Stage P into KP as [q][k]
#pragma unroll
        for (int i = 0; i < 4; i++) {
            float4 pv;
            pv.x = s[i][0]; pv.y = s[i][1]; pv.z = s[i][2]; pv.w = s[i][3];
            *(float4*)&KP[(tq << 2) + i][tk << 2] = pv;
        }
        __syncthreads();

        // Rescale accumulators
#pragma unroll
        for (int i = 0; i < 4; i++)
#pragma unroll
            for (int j = 0; j < 4; j++)
                o[i][j] *= sf[i];

        // PV: o[4q][4d] += P[q][k] * V[k][d]
#pragma unroll 16
        for (int k = 0; k < 64; k++) {
            float p0 = KP[(tq << 2) + 0][k];
            float p1 = KP[(tq << 2) + 1][k];
            float p2 = KP[(tq << 2) + 2][k];
            float p3 = KP[(tq << 2) + 3][k];
            float4 vv = *(const float4*)&Vs[k][tk << 2];
            o[0][0] += p0 * vv.x; o[0][1] += p0 * vv.y; o[0][2] += p0 * vv.z; o[0][3] += p0 * vv.w;
            o[1][0] += p1 * vv.x; o[1][1] += p1 * vv.y; o[1][2] += p1 * vv.z; o[1][3] += p1 * vv.w;
            o[2][0] += p2 * vv.x; o[2][1] += p2 * vv.y; o[2][2] += p2 * vv.z; o[2][3] += p2 * vv.w;
            o[3][0] += p3 * vv.x; o[3][1] += p3 * vv.y; o[3][2] += p3 * vv.z; o[3][3] += p3 * vv.w;
        }
    }

    // Finalize and store to g_o [B*S, H*D]
#pragma unroll
    for (int i = 0; i < 4; i++) {
        float inv = 1.f / l[i];
        float4 ov;
        ov.x = o[i][0] * inv; ov.y = o[i][1] * inv;
        ov.z = o[i][2] * inv; ov.w = o[i][3] * inv;
        int row = b * SEQ + qb * 64 + (tq << 2) + i;
        *(float4*)(O + (size_t)row * HIDDEN + h * HDIM + (tk << 2)) = ov;
    }
}

// ---------------------------------------------------------------------------
extern "C" void kernel_launch(void* const* d_in, const int* in_sizes, int n_in,
                              void* d_out, int out_size)
{
    const float* x  = (const float*)d_in[0];
    const float* wq = (const float*)d_in[1];
    const float* bq = (const float*)d_in[2];
    const float* wk = (const float*)d_in[3];
    const float* bk = (const float*)d_in[4];
    const float* wv = (const float*)d_in[5];
    const float* bv = (const float*)d_in[6];
    const float* wo = (const float*)d_in[7];
    const float* bo = (const float*)d_in[8];
    float* out = (float*)d_out;

    float *q, *k, *v, *o;
    cudaGetSymbolAddress((void**)&q, g_q);
    cudaGetSymbolAddress((void**)&k, g_k);
    cudaGetSymbolAddress((void**)&v, g_v);
    cudaGetSymbolAddress((void**)&o, g_o);

    // Projections
    gemm_bias_kernel<<<dim3(HIDDEN / BN, MROWS / BM), 256>>>(x, wq, bq, q, MROWS, HIDDEN, HIDDEN);
    gemm_bias_kernel<<<dim3(KVDIM  / BN, MROWS / BM), 256>>>(x, wk, bk, k, MROWS, KVDIM,  HIDDEN);
    gemm_bias_kernel<<<dim3(KVDIM  / BN, MROWS / BM), 256>>>(x, wv, bv, v, MROWS, KVDIM,  HIDDEN);

    // Attention
    attn_kernel<<<dim3(SEQ / 64, NHEADS, BATCH), 256>>>(q, k, v, o);

    // Output projection
    gemm_bias_kernel<<<dim3(HIDDEN / BN, MROWS / BM), 256>>>(o, wo, bo, out, MROWS, HIDDEN, HIDDEN);
}

// round 5
// speedup vs baseline: 1.0220x; 1.0220x over previous
#include <cuda_runtime.h>
#include <cuda_bf16.h>
#include <cstdint>

// Problem constants
#define BATCH 2
#define SEQ 2048
#define HIDDEN 2048
#define NHEADS 32
#define NKV 8
#define HDIM 64
#define KVDIM 512
#define MROWS (BATCH * SEQ)   // 4096

// Scratch (allocation-free rule: __device__ globals)
__device__ float g_q[MROWS * HIDDEN];
__device__ float g_k[MROWS * KVDIM];
__device__ float g_v[MROWS * KVDIM];
__device__ float g_o[MROWS * HIDDEN];

__device__ __forceinline__ uint32_t f2tf32(float f) {
    uint32_t r;
    asm("cvt.rna.tf32.f32 %0, %1;" : "=r"(r) : "f"(f));
    return r;
}

__device__ __forceinline__ void mma_tf32(float* d, const uint32_t* a, const uint32_t* b) {
    asm volatile(
        "mma.sync.aligned.m16n8k8.row.col.f32.tf32.tf32.f32 "
        "{%0,%1,%2,%3}, {%4,%5,%6,%7}, {%8,%9}, {%0,%1,%2,%3};"
        : "+f"(d[0]), "+f"(d[1]), "+f"(d[2]), "+f"(d[3])
        : "r"(a[0]), "r"(a[1]), "r"(a[2]), "r"(a[3]), "r"(b[0]), "r"(b[1]));
}

// ---------------------------------------------------------------------------
// tf32 tensor-core GEMM: C[M,N] = A[M,K] @ W[N,K]^T + bias[N]
// CTA tile 128x128, BK=16, 256 threads (8 warps, 2x4), warp tile 64x32.
// Fragments per PTX m16n8k8 row.col layout; smem stride 20 => conflict-free.
// ---------------------------------------------------------------------------
#define TSTRIDE 20

__global__ __launch_bounds__(256, 2) void gemm_mma(
    const float* __restrict__ A, const float* __restrict__ W,
    const float* __restrict__ bias, float* __restrict__ C,
    int M, int N, int K)
{
    __shared__ uint32_t As[2][128 * TSTRIDE];
    __shared__ uint32_t Ws[2][128 * TSTRIDE];

    const int tid = threadIdx.x;
    const int wid = tid >> 5;
    const int lane = tid & 31;
    const int g = lane >> 2;     // group id 0..7
    const int t = lane & 3;      // thread-in-group 0..3
    const int wm = (wid & 1) * 64;   // warp m offset
    const int wn = (wid >> 1) * 32;  // warp n offset
    const int bm = blockIdx.y * 128;
    const int bn = blockIdx.x * 128;

    // LDG mapping: 512 float4 per operand tile, 2 per thread
    const int r0 = (tid + 0 * 256) >> 2, c0 = ((tid + 0 * 256) & 3) << 2;
    const int r1 = (tid + 1 * 256) >> 2, c1 = ((tid + 1 * 256) & 3) << 2;

    float4 ra0, ra1, rb0, rb1;
    auto ldg_tile = [&](int k0) {
        ra0 = *(const float4*)(A + (size_t)(bm + r0) * K + k0 + c0);
        ra1 = *(const float4*)(A + (size_t)(bm + r1) * K + k0 + c1);
        rb0 = *(const float4*)(W + (size_t)(bn + r0) * K + k0 + c0);
        rb1 = *(const float4*)(W + (size_t)(bn + r1) * K + k0 + c1);
    };
    auto sts_tile = [&](int s) {
        uint32_t* pa0 = &As[s][r0 * TSTRIDE + c0];
        pa0[0] = f2tf32(ra0.x); pa0[1] = f2tf32(ra0.y); pa0[2] = f2tf32(ra0.z); pa0[3] = f2tf32(ra0.w);
        uint32_t* pa1 = &As[s][r1 * TSTRIDE + c1];
        pa1[0] = f2tf32(ra1.x); pa1[1] = f2tf32(ra1.y); pa1[2] = f2tf32(ra1.z); pa1[3] = f2tf32(ra1.w);
        uint32_t* pb0 = &Ws[s][r0 * TSTRIDE + c0];
        pb0[0] = f2tf32(rb0.x); pb0[1] = f2tf32(rb0.y); pb0[2] = f2tf32(rb0.z); pb0[3] = f2tf32(rb0.w);
        uint32_t* pb1 = &Ws[s][r1 * TSTRIDE + c1];
        pb1[0] = f2tf32(rb1.x); pb1[1] = f2tf32(rb1.y); pb1[2] = f2tf32(rb1.z); pb1[3] = f2tf32(rb1.w);
    };

    float acc[4][4][4] = {};   // [mi][ni][reg]

    const int NT = K >> 4;
    ldg_tile(0);

    for (int kt = 0; kt < NT; kt++) {
        const int s = kt & 1;
        sts_tile(s);
        __syncthreads();
        if (kt + 1 < NT) ldg_tile((kt + 1) << 4);

#pragma unroll
        for (int kk = 0; kk < 2; kk++) {
            const int kc = kk * 8 + t;
            uint32_t af[4][4];
#pragma unroll
            for (int mi = 0; mi < 4; mi++) {
                const int row = wm + mi * 16 + g;
                af[mi][0] = As[s][(row    ) * TSTRIDE + kc];
                af[mi][1] = As[s][(row + 8) * TSTRIDE + kc];
                af[mi][2] = As[s][(row    ) * TSTRIDE + kc + 4];
                af[mi][3] = As[s][(row + 8) * TSTRIDE + kc + 4];
            }
            uint32_t bf[4][2];
#pragma unroll
            for (int ni = 0; ni < 4; ni++) {
                const int row = wn + ni * 8 + g;
                bf[ni][0] = Ws[s][row * TSTRIDE + kc];
                bf[ni][1] = Ws[s][row * TSTRIDE + kc + 4];
            }
#pragma unroll
            for (int mi = 0; mi < 4; mi++)
#pragma unroll
                for (int ni = 0; ni < 4; ni++)
                    mma_tf32(acc[mi][ni], af[mi], bf[ni]);
        }
        __syncthreads();
    }

    // Epilogue: C frag rows g/g+8, cols t*2, t*2+1 within each 16x8 tile
#pragma unroll
    for (int mi = 0; mi < 4; mi++) {
#pragma unroll
        for (int ni = 0; ni < 4; ni++) {
            const int col = bn + wn + ni * 8 + t * 2;
            const float bx = __ldg(bias + col);
            const float by = __ldg(bias + col + 1);
            const int rr0 = bm + wm + mi * 16 + g;
            float2 v0 = {acc[mi][ni][0] + bx, acc[mi][ni][1] + by};
            float2 v1 = {acc[mi][ni][2] + bx, acc[mi][ni][3] + by};
            *(float2*)(C + (size_t)rr0 * N + col) = v0;
            *(float2*)(C + (size_t)(rr0 + 8) * N + col) = v1;
        }
    }
}

// ---------------------------------------------------------------------------
// Flash attention (fp32) — unchanged from R1 (verified correct).
// ---------------------------------------------------------------------------
__global__ __launch_bounds__(256) void attn_kernel(
    const float* __restrict__ Q, const float* __restrict__ Kg,
    const float* __restrict__ Vg, float* __restrict__ O)
{
    __shared__ float Qs[64][64];
    __shared__ float KP[64][64];
    __shared__ float Vs[64][64];

    const int tid = threadIdx.x;
    const int qb = blockIdx.x;
    const int h  = blockIdx.y;
    const int b  = blockIdx.z;
    const int kvh = h >> 2;
    const int tq = tid >> 4;
    const int tk = tid & 15;
    const float scale = 0.125f;

    for (int i = tid; i < 64 * 16; i += 256) {
        int r = i >> 4;
        int c = (i & 15) << 2;
        float4 v = *(const float4*)(Q + (size_t)(b * SEQ + qb * 64 + r) * HIDDEN + h * HDIM + c);
        float4 s;
        s.x = v.x * scale; s.y = v.y * scale; s.z = v.z * scale; s.w = v.w * scale;
        *(float4*)&Qs[r][c] = s;
    }

    float o[4][4] = {};
    float m[4] = {-1e30f, -1e30f, -1e30f, -1e30f};
    float l[4] = {};

    for (int jb = 0; jb < SEQ / 64; jb++) {
        __syncthreads();
        for (int i = tid; i < 64 * 16; i += 256) {
            int r = i >> 4;
            int c = (i & 15) << 2;
            size_t basei = (size_t)(b * SEQ + jb * 64 + r) * KVDIM + kvh * HDIM + c;
            float4 kv = *(const float4*)(Kg + basei);
            KP[c + 0][r] = kv.x; KP[c + 1][r] = kv.y;
            KP[c + 2][r] = kv.z; KP[c + 3][r] = kv.w;
            float4 vv = *(const float4*)(Vg + basei);
            *(float4*)&Vs[r][c] = vv;
        }
        __syncthreads();

        float s[4][4] = {};
#pragma unroll 16
        for (int d = 0; d < 64; d++) {
            float a0 = Qs[(tq << 2) + 0][d];
            float a1 = Qs[(tq << 2) + 1][d];
            float a2 = Qs[(tq << 2) + 2][d];
            float a3 = Qs[(tq << 2) + 3][d];
            float4 kk = *(const float4*)&KP[d][tk << 2];
            s[0][0] += a0 * kk.x; s[0][1] += a0 * kk.y; s[0][2] += a0 * kk.z; s[0][3] += a0 * kk.w;
            s[1][0] += a1 * kk.x; s[1][1] += a1 * kk.y; s[1][2] += a1 * kk.z; s[1][3] += a1 * kk.w;
            s[2][0] += a2 * kk.x; s[2][1] += a2 * kk.y; s[2][2] += a2 * kk.z; s[2][3] += a2 * kk.w;
            s[3][0] += a3 * kk.x; s[3][1] += a3 * kk.y; s[3][2] += a3 * kk.z; s[3][3] += a3 * kk.w;
        }

        float sf[4];
#pragma unroll
        for (int i = 0; i < 4; i++) {
            float mx = fmaxf(fmaxf(s[i][0], s[i][1]), fmaxf(s[i][2], s[i][3]));
#pragma unroll
            for (int off = 8; off > 0; off >>= 1)
                mx = fmaxf(mx, __shfl_xor_sync(0xffffffffu, mx, off));
            float mnew = fmaxf(m[i], mx);
            sf[i] = __expf(m[i] - mnew);
            float rs = 0.f;
#pragma unroll
            for (int j = 0; j < 4; j++) {
                s[i][j] = __expf(s[i][j] - mnew);
                rs += s[i][j];
            }
#pragma unroll
            for (int off = 8; off > 0; off >>= 1)
                rs += __shfl_xor_sync(0xffffffffu, rs, off);
            l[i] = l[i] * sf[i] + rs;
            m[i] = mnew;
        }

        __syncthreads();
#pragma unroll
        for (int i = 0; i < 4; i++) {
            float4 pv;
            pv.x = s[i][0]; pv.y = s[i][1]; pv.z = s[i][2]; pv.w = s[i][3];
            *(float4*)&KP[(tq << 2) + i][tk << 2] = pv;
        }
        __syncthreads();

#pragma unroll
        for (int i = 0; i < 4; i++)
#pragma unroll
            for (int j = 0; j < 4; j++)
                o[i][j] *= sf[i];

#pragma unroll 16
        for (int k = 0; k < 64; k++) {
            float p0 = KP[(tq << 2) + 0][k];
            float p1 = KP[(tq << 2) + 1][k];
            float p2 = KP[(tq << 2) + 2][k];
            float p3 = KP[(tq << 2) + 3][k];
            float4 vv = *(const float4*)&Vs[k][tk << 2];
            o[0][0] += p0 * vv.x; o[0][1] += p0 * vv.y; o[0][2] += p0 * vv.z; o[0][3] += p0 * vv.w;
            o[1][0] += p1 * vv.x; o[1][1] += p1 * vv.y; o[1][2] += p1 * vv.z; o[1][3] += p1 * vv.w;
            o[2][0] += p2 * vv.x; o[2][1] += p2 * vv.y; o[2][2] += p2 * vv.z; o[2][3] += p2 * vv.w;
            o[3][0] += p3 * vv.x; o[3][1] += p3 * vv.y; o[3][2] += p3 * vv.z; o[3][3] += p3 * vv.w;
        }
    }

#pragma unroll
    for (int i = 0; i < 4; i++) {
        float inv = 1.f / l[i];
        float4 ov;
        ov.x = o[i][0] * inv; ov.y = o[i][1] * inv;
        ov.z = o[i][2] * inv; ov.w = o[i][3] * inv;
        int row = b * SEQ + qb * 64 + (tq << 2) + i;
        *(float4*)(O + (size_t)row * HIDDEN + h * HDIM + (tk << 2)) = ov;
    }
}

// ---------------------------------------------------------------------------
extern "C" void kernel_launch(void* const* d_in, const int* in_sizes, int n_in,
                              void* d_out, int out_size)
{
    const float* x  = (const float*)d_in[0];
    const float* wq = (const float*)d_in[1];
    const float* bq = (const float*)d_in[2];
    const float* wk = (const float*)d_in[3];
    const float* bk = (const float*)d_in[4];
    const float* wv = (const float*)d_in[5];
    const float* bv = (const float*)d_in[6];
    const float* wo = (const float*)d_in[7];
    const float* bo = (const float*)d_in[8];
    float* out = (float*)d_out;

    float *q, *k, *v, *o;
    cudaGetSymbolAddress((void**)&q, g_q);
    cudaGetSymbolAddress((void**)&k, g_k);
    cudaGetSymbolAddress((void**)&v, g_v);
    cudaGetSymbolAddress((void**)&o, g_o);

    gemm_mma<<<dim3(HIDDEN / 128, MROWS / 128), 256>>>(x, wq, bq, q, MROWS, HIDDEN, HIDDEN);
    gemm_mma<<<dim3(KVDIM  / 128, MROWS / 128), 256>>>(x, wk, bk, k, MROWS, KVDIM,  HIDDEN);
    gemm_mma<<<dim3(KVDIM  / 128, MROWS / 128), 256>>>(x, wv, bv, v, MROWS, KVDIM,  HIDDEN);

    attn_kernel<<<dim3(SEQ / 64, NHEADS, BATCH), 256>>>(q, k, v, o);

    gemm_mma<<<dim3(HIDDEN / 128, MROWS / 128), 256>>>(o, wo, bo, out, MROWS, HIDDEN, HIDDEN);
}

// round 6
// speedup vs baseline: 3.5697x; 3.4927x over previous
#include <cuda_runtime.h>
#include <cuda_bf16.h>
#include <cstdint>

// Problem constants
#define BATCH 2
#define SEQ 2048
#define HIDDEN 2048
#define NHEADS 32
#define NKV 8
#define HDIM 64
#define KVDIM 512
#define MROWS (BATCH * SEQ)   // 4096

// Scratch (allocation-free rule: __device__ globals)
__device__ float g_q[MROWS * HIDDEN];
__device__ float g_k[MROWS * KVDIM];
__device__ float g_v[MROWS * KVDIM];
__device__ float g_o[MROWS * HIDDEN];
__device__ float g_xc[MROWS * HIDDEN];      // tf32-rounded x
__device__ float g_wqc[HIDDEN * HIDDEN];
__device__ float g_wkc[KVDIM * HIDDEN];
__device__ float g_wvc[KVDIM * HIDDEN];
__device__ float g_woc[HIDDEN * HIDDEN];

__device__ __forceinline__ float rndtf32(float f) {
    uint32_t r;
    asm("cvt.rna.tf32.f32 %0, %1;" : "=r"(r) : "f"(f));
    return __uint_as_float(r);
}

__device__ __forceinline__ void mma_tf32(float* d, const uint32_t* a, const uint32_t* b) {
    asm volatile(
        "mma.sync.aligned.m16n8k8.row.col.f32.tf32.tf32.f32 "
        "{%0,%1,%2,%3}, {%4,%5,%6,%7}, {%8,%9}, {%0,%1,%2,%3};"
        : "+f"(d[0]), "+f"(d[1]), "+f"(d[2]), "+f"(d[3])
        : "r"(a[0]), "r"(a[1]), "r"(a[2]), "r"(a[3]), "r"(b[0]), "r"(b[1]));
}

__device__ __forceinline__ uint32_t smem_u32(const void* p) {
    uint32_t a;
    asm("{ .reg .u64 t; cvta.to.shared.u64 t, %1; cvt.u32.u64 %0, t; }" : "=r"(a) : "l"(p));
    return a;
}

__device__ __forceinline__ void cpasync16(uint32_t dst, const float* src) {
    asm volatile("cp.async.ca.shared.global [%0], [%1], 16;" :: "r"(dst), "l"(src));
}

// ---------------------------------------------------------------------------
// Elementwise tf32 rounding (preprocess so GEMM can cp.async raw tiles)
// ---------------------------------------------------------------------------
__global__ void cvt_tf32(const float4* __restrict__ in, float4* __restrict__ out, int n4) {
    int i = blockIdx.x * blockDim.x + threadIdx.x;
    if (i < n4) {
        float4 v = in[i];
        v.x = rndtf32(v.x); v.y = rndtf32(v.y);
        v.z = rndtf32(v.z); v.w = rndtf32(v.w);
        out[i] = v;
    }
}

// ---------------------------------------------------------------------------
// tf32 tensor-core GEMM: C[M,N] = A[M,K] @ W[N,K]^T + bias[N]
// Inputs pre-rounded to tf32. cp.async 3-stage pipeline, BK=16.
// CTA 128x128, 256 threads (8 warps 2x4), warp tile 64x32 (validated mapping).
// SMEM: 3 stages x (A 128x20 + B 128x20) words = 61440 B.
// ---------------------------------------------------------------------------
#define TS 20
#define GSM_BYTES (3 * 2 * 128 * TS * 4)

template <bool ROUND>
__global__ __launch_bounds__(256) void gemm_mma(
    const float* __restrict__ A, const float* __restrict__ W,
    const float* __restrict__ bias, float* __restrict__ C,
    int M, int N, int K)
{
    extern __shared__ uint32_t sh[];
    const uint32_t sbase = smem_u32(sh);

    const int tid = threadIdx.x;
    const int wid = tid >> 5;
    const int lane = tid & 31;
    const int g = lane >> 2;
    const int t = lane & 3;
    const int wm = (wid & 1) * 64;
    const int wn = (wid >> 1) * 32;
    const int bm = blockIdx.y * 128;
    const int bn = blockIdx.x * 128;

    const int NT = K >> 4;

    auto issue = [&](int kt, int s) {
        const int k0 = kt << 4;
        const uint32_t so = (uint32_t)s * 5120u;
#pragma unroll
        for (int j = 0; j < 2; j++) {
            int idx = j * 256 + tid;
            int r = idx >> 2, c4 = idx & 3;
            uint32_t off = (so + (uint32_t)(r * TS + c4 * 4)) * 4u;
            cpasync16(sbase + off, A + (size_t)(bm + r) * K + k0 + c4 * 4);
            cpasync16(sbase + off + 2560u * 4u, W + (size_t)(bn + r) * K + k0 + c4 * 4);
        }
        asm volatile("cp.async.commit_group;" ::: "memory");
    };

    issue(0, 0);
    issue(1, 1);

    float acc[4][4][4] = {};

    for (int kt = 0; kt < NT; kt++) {
        asm volatile("cp.async.wait_group %0;" :: "n"(1) : "memory");
        __syncthreads();
        if (kt + 2 < NT) issue(kt + 2, (kt + 2) % 3);

        const uint32_t* As = sh + (kt % 3) * 5120;
        const uint32_t* Ws = As + 2560;

#pragma unroll
        for (int kk = 0; kk < 2; kk++) {
            const int kc = kk * 8 + t;
            uint32_t af[4][4];
#pragma unroll
            for (int mi = 0; mi < 4; mi++) {
                const int row = wm + mi * 16 + g;
                af[mi][0] = As[(row    ) * TS + kc];
                af[mi][1] = As[(row + 8) * TS + kc];
                af[mi][2] = As[(row    ) * TS + kc + 4];
                af[mi][3] = As[(row + 8) * TS + kc + 4];
            }
            uint32_t bf[4][2];
#pragma unroll
            for (int ni = 0; ni < 4; ni++) {
                const int row = wn + ni * 8 + g;
                bf[ni][0] = Ws[row * TS + kc];
                bf[ni][1] = Ws[row * TS + kc + 4];
            }
#pragma unroll
            for (int mi = 0; mi < 4; mi++)
#pragma unroll
                for (int ni = 0; ni < 4; ni++)
                    mma_tf32(acc[mi][ni], af[mi], bf[ni]);
        }
    }

#pragma unroll
    for (int mi = 0; mi < 4; mi++) {
#pragma unroll
        for (int ni = 0; ni < 4; ni++) {
            const int col = bn + wn + ni * 8 + t * 2;
            const float bx = __ldg(bias + col);
            const float by = __ldg(bias + col + 1);
            const int rr0 = bm + wm + mi * 16 + g;
            float2 v0, v1;
            v0.x = acc[mi][ni][0] + bx; v0.y = acc[mi][ni][1] + by;
            v1.x = acc[mi][ni][2] + bx; v1.y = acc[mi][ni][3] + by;
            if (ROUND) {
                v0.x = rndtf32(v0.x); v0.y = rndtf32(v0.y);
                v1.x = rndtf32(v1.x); v1.y = rndtf32(v1.y);
            }
            *(float2*)(C + (size_t)rr0 * N + col) = v0;
            *(float2*)(C + (size_t)(rr0 + 8) * N + col) = v1;
        }
    }
}

// ---------------------------------------------------------------------------
// Tensor-core flash attention (tf32 mma, fp32 accum).
// CTA = (128-query tile, head, batch). 256 threads = 8 warps x 16 q-rows.
// Key tiles of 64. Q/K/V pre-rounded tf32 (gemm epilogue).
// SMEM (words): Qs 128x68 | Ks 64x68 | Vs 64x72 | Ps 8x(16x68)  = 105472 B.
// ---------------------------------------------------------------------------
#define ASM_BYTES ((128 * 68 + 64 * 68 + 64 * 72 + 8 * 16 * 68) * 4)

__global__ __launch_bounds__(256) void attn_mma(
    const float* __restrict__ Q, const float* __restrict__ Kg,
    const float* __restrict__ Vg, float* __restrict__ O)
{
    extern __shared__ float sm[];
    float* Qs = sm;                       // stride 68
    float* Ks = Qs + 128 * 68;            // stride 68
    float* Vs = Ks + 64 * 68;             // stride 72
    float* Ps = Vs + 64 * 72;             // per-warp 16x68

    const int tid = threadIdx.x;
    const int wid = tid >> 5;
    const int lane = tid & 31;
    const int g = lane >> 2;
    const int t = lane & 3;
    const int qb = blockIdx.x;
    const int h  = blockIdx.y;
    const int b  = blockIdx.z;
    const int kvh = h >> 2;

    // Load Q tile (scale by 1/8: exact power of two, keeps tf32)
#pragma unroll
    for (int j = 0; j < 8; j++) {
        int idx = j * 256 + tid;
        int r = idx >> 4, c = (idx & 15) << 2;
        float4 v = *(const float4*)(Q + (size_t)(b * SEQ + qb * 128 + r) * HIDDEN + h * HDIM + c);
        v.x *= 0.125f; v.y *= 0.125f; v.z *= 0.125f; v.w *= 0.125f;
        *(float4*)&Qs[r * 68 + c] = v;
    }

    float* Pw = Ps + wid * 16 * 68;
    const int qr = wid * 16 + g;

    float acc_o[8][4] = {};
    float m0 = -1e30f, m1 = -1e30f, l0 = 0.f, l1 = 0.f;

    for (int jb = 0; jb < SEQ / 64; jb++) {
        __syncthreads();
        // Load K,V tiles
#pragma unroll
        for (int j = 0; j < 4; j++) {
            int idx = j * 256 + tid;
            int r = idx >> 4, c = (idx & 15) << 2;
            size_t gb = (size_t)(b * SEQ + jb * 64 + r) * KVDIM + kvh * HDIM + c;
            *(float4*)&Ks[r * 68 + c] = *(const float4*)(Kg + gb);
            *(float4*)&Vs[r * 72 + c] = *(const float4*)(Vg + gb);
        }
        __syncthreads();

        // S = Q K^T  (warp: 16 x 64)
        float acc_s[8][4] = {};
#pragma unroll
        for (int kk = 0; kk < 8; kk++) {
            const int kc = kk * 8 + t;
            uint32_t af[4];
            af[0] = __float_as_uint(Qs[qr * 68 + kc]);
            af[1] = __float_as_uint(Qs[(qr + 8) * 68 + kc]);
            af[2] = __float_as_uint(Qs[qr * 68 + kc + 4]);
            af[3] = __float_as_uint(Qs[(qr + 8) * 68 + kc + 4]);
#pragma unroll
            for (int ni = 0; ni < 8; ni++) {
                uint32_t bf[2];
                bf[0] = __float_as_uint(Ks[(ni * 8 + g) * 68 + kc]);
                bf[1] = __float_as_uint(Ks[(ni * 8 + g) * 68 + kc + 4]);
                mma_tf32(acc_s[ni], af, bf);
            }
        }

        // Fragment online softmax. Thread owns rows (qr, qr+8), 16 cols each.
        float mx0 = -1e30f, mx1 = -1e30f;
#pragma unroll
        for (int ni = 0; ni < 8; ni++) {
            mx0 = fmaxf(mx0, fmaxf(acc_s[ni][0], acc_s[ni][1]));
            mx1 = fmaxf(mx1, fmaxf(acc_s[ni][2], acc_s[ni][3]));
        }
        mx0 = fmaxf(mx0, __shfl_xor_sync(0xffffffffu, mx0, 1));
        mx0 = fmaxf(mx0, __shfl_xor_sync(0xffffffffu, mx0, 2));
        mx1 = fmaxf(mx1, __shfl_xor_sync(0xffffffffu, mx1, 1));
        mx1 = fmaxf(mx1, __shfl_xor_sync(0xffffffffu, mx1, 2));
        const float mn0 = fmaxf(m0, mx0);
        const float mn1 = fmaxf(m1, mx1);
        const float sf0 = __expf(m0 - mn0);
        const float sf1 = __expf(m1 - mn1);
        m0 = mn0; m1 = mn1;

        float rs0 = 0.f, rs1 = 0.f;
#pragma unroll
        for (int ni = 0; ni < 8; ni++) {
            float p0 = __expf(acc_s[ni][0] - mn0);
            float p1 = __expf(acc_s[ni][1] - mn0);
            float p2 = __expf(acc_s[ni][2] - mn1);
            float p3 = __expf(acc_s[ni][3] - mn1);
            rs0 += p0 + p1;
            rs1 += p2 + p3;
            float2 w0, w1;
            w0.x = rndtf32(p0); w0.y = rndtf32(p1);
            w1.x = rndtf32(p2); w1.y = rndtf32(p3);
            *(float2*)&Pw[g * 68 + ni * 8 + 2 * t] = w0;
            *(float2*)&Pw[(g + 8) * 68 + ni * 8 + 2 * t] = w1;
        }
        rs0 += __shfl_xor_sync(0xffffffffu, rs0, 1);
        rs0 += __shfl_xor_sync(0xffffffffu, rs0, 2);
        rs1 += __shfl_xor_sync(0xffffffffu, rs1, 1);
        rs1 += __shfl_xor_sync(0xffffffffu, rs1, 2);
        l0 = l0 * sf0 + rs0;
        l1 = l1 * sf1 + rs1;

#pragma unroll
        for (int dn = 0; dn < 8; dn++) {
            acc_o[dn][0] *= sf0; acc_o[dn][1] *= sf0;
            acc_o[dn][2] *= sf1; acc_o[dn][3] *= sf1;
        }
        __syncwarp();  // P STS visible across lanes (warp-private tile)

        // O += P V   (A = P from per-warp smem, B[n][k] = V[k][n] from Vs)
#pragma unroll
        for (int kk = 0; kk < 8; kk++) {
            const int kc = kk * 8 + t;
            uint32_t af[4];
            af[0] = __float_as_uint(Pw[g * 68 + kc]);
            af[1] = __float_as_uint(Pw[(g + 8) * 68 + kc]);
            af[2] = __float_as_uint(Pw[g * 68 + kc + 4]);
            af[3] = __float_as_uint(Pw[(g + 8) * 68 + kc + 4]);
#pragma unroll
            for (int dn = 0; dn < 8; dn++) {
                uint32_t bf[2];
                bf[0] = __float_as_uint(Vs[(kk * 8 + t) * 72 + dn * 8 + g]);
                bf[1] = __float_as_uint(Vs[(kk * 8 + t + 4) * 72 + dn * 8 + g]);
                mma_tf32(acc_o[dn], af, bf);
            }
        }
        __syncwarp();
    }

    // Epilogue: normalize, round to tf32 (feeds O-proj mma), store.
    const float i0 = 1.f / l0;
    const float i1 = 1.f / l1;
    const int row0 = b * SEQ + qb * 128 + qr;
#pragma unroll
    for (int dn = 0; dn < 8; dn++) {
        const int col = h * HDIM + dn * 8 + 2 * t;
        float2 v0, v1;
        v0.x = rndtf32(acc_o[dn][0] * i0); v0.y = rndtf32(acc_o[dn][1] * i0);
        v1.x = rndtf32(acc_o[dn][2] * i1); v1.y = rndtf32(acc_o[dn][3] * i1);
        *(float2*)(O + (size_t)row0 * HIDDEN + col) = v0;
        *(float2*)(O + (size_t)(row0 + 8) * HIDDEN + col) = v1;
    }
}

// ---------------------------------------------------------------------------
extern "C" void kernel_launch(void* const* d_in, const int* in_sizes, int n_in,
                              void* d_out, int out_size)
{
    const float* x  = (const float*)d_in[0];
    const float* wq = (const float*)d_in[1];
    const float* bq = (const float*)d_in[2];
    const float* wk = (const float*)d_in[3];
    const float* bk = (const float*)d_in[4];
    const float* wv = (const float*)d_in[5];
    const float* bv = (const float*)d_in[6];
    const float* wo = (const float*)d_in[7];
    const float* bo = (const float*)d_in[8];
    float* out = (float*)d_out;

    float *q, *k, *v, *o, *xc, *wqc, *wkc, *wvc, *woc;
    cudaGetSymbolAddress((void**)&q, g_q);
    cudaGetSymbolAddress((void**)&k, g_k);
    cudaGetSymbolAddress((void**)&v, g_v);
    cudaGetSymbolAddress((void**)&o, g_o);
    cudaGetSymbolAddress((void**)&xc, g_xc);
    cudaGetSymbolAddress((void**)&wqc, g_wqc);
    cudaGetSymbolAddress((void**)&wkc, g_wkc);
    cudaGetSymbolAddress((void**)&wvc, g_wvc);
    cudaGetSymbolAddress((void**)&woc, g_woc);

    cudaFuncSetAttribute(gemm_mma<true>,  cudaFuncAttributeMaxDynamicSharedMemorySize, GSM_BYTES);
    cudaFuncSetAttribute(gemm_mma<false>, cudaFuncAttributeMaxDynamicSharedMemorySize, GSM_BYTES);
    cudaFuncSetAttribute(attn_mma,        cudaFuncAttributeMaxDynamicSharedMemorySize, ASM_BYTES);

    // Pre-round inputs to tf32 so GEMM can stream raw tiles via cp.async
    cvt_tf32<<<(MROWS * HIDDEN / 4 + 255) / 256, 256>>>((const float4*)x,  (float4*)xc,  MROWS * HIDDEN / 4);
    cvt_tf32<<<(HIDDEN * HIDDEN / 4 + 255) / 256, 256>>>((const float4*)wq, (float4*)wqc, HIDDEN * HIDDEN / 4);
    cvt_tf32<<<(KVDIM * HIDDEN / 4 + 255) / 256, 256>>>((const float4*)wk, (float4*)wkc, KVDIM * HIDDEN / 4);
    cvt_tf32<<<(KVDIM * HIDDEN / 4 + 255) / 256, 256>>>((const float4*)wv, (float4*)wvc, KVDIM * HIDDEN / 4);
    cvt_tf32<<<(HIDDEN * HIDDEN / 4 + 255) / 256, 256>>>((const float4*)wo, (float4*)woc, HIDDEN * HIDDEN / 4);

    // Projections (outputs tf32-rounded: they feed attention mma)
    gemm_mma<true><<<dim3(HIDDEN / 128, MROWS / 128), 256, GSM_BYTES>>>(xc, wqc, bq, q, MROWS, HIDDEN, HIDDEN);
    gemm_mma<true><<<dim3(KVDIM  / 128, MROWS / 128), 256, GSM_BYTES>>>(xc, wkc, bk, k, MROWS, KVDIM,  HIDDEN);
    gemm_mma<true><<<dim3(KVDIM  / 128, MROWS / 128), 256, GSM_BYTES>>>(xc, wvc, bv, v, MROWS, KVDIM,  HIDDEN);

    // Attention (tensor core)
    attn_mma<<<dim3(SEQ / 128, NHEADS, BATCH), 256, ASM_BYTES>>>(q, k, v, o);

    // Output projection (fp32 output, no rounding)
    gemm_mma<false><<<dim3(HIDDEN / 128, MROWS / 128), 256, GSM_BYTES>>>(o, woc, bo, out, MROWS, HIDDEN, HIDDEN);
}

// round 7
// speedup vs baseline: 3.8340x; 1.0740x over previous
#include <cuda_runtime.h>
#include <cuda_bf16.h>
#include <cstdint>

// Problem constants
#define BATCH 2
#define SEQ 2048
#define HIDDEN 2048
#define NHEADS 32
#define NKV 8
#define HDIM 64
#define KVDIM 512
#define MROWS (BATCH * SEQ)   // 4096
#define NQKV (HIDDEN + 2 * KVDIM)  // 3072

// Scratch (allocation-free rule: __device__ globals)
__device__ float g_q[MROWS * HIDDEN];
__device__ float g_k[MROWS * KVDIM];
__device__ float g_v[MROWS * KVDIM];
__device__ float g_o[MROWS * HIDDEN];
__device__ float g_xc[MROWS * HIDDEN];       // tf32-rounded x
__device__ float g_wqkv[NQKV * HIDDEN];      // tf32-rounded [wq; wk; wv]
__device__ float g_woc[HIDDEN * HIDDEN];     // tf32-rounded wo

__device__ __forceinline__ float rndtf32(float f) {
    uint32_t r;
    asm("cvt.rna.tf32.f32 %0, %1;" : "=r"(r) : "f"(f));
    return __uint_as_float(r);
}

__device__ __forceinline__ void mma_tf32(float* d, const uint32_t* a, const uint32_t* b) {
    asm volatile(
        "mma.sync.aligned.m16n8k8.row.col.f32.tf32.tf32.f32 "
        "{%0,%1,%2,%3}, {%4,%5,%6,%7}, {%8,%9}, {%0,%1,%2,%3};"
        : "+f"(d[0]), "+f"(d[1]), "+f"(d[2]), "+f"(d[3])
        : "r"(a[0]), "r"(a[1]), "r"(a[2]), "r"(a[3]), "r"(b[0]), "r"(b[1]));
}

__device__ __forceinline__ uint32_t smem_u32(const void* p) {
    uint32_t a;
    asm("{ .reg .u64 t; cvta.to.shared.u64 t, %1; cvt.u32.u64 %0, t; }" : "=r"(a) : "l"(p));
    return a;
}

__device__ __forceinline__ void cpasync16(uint32_t dst, const float* src) {
    asm volatile("cp.async.ca.shared.global [%0], [%1], 16;" :: "r"(dst), "l"(src));
}

// ---------------------------------------------------------------------------
// Elementwise tf32 rounding
// ---------------------------------------------------------------------------
__global__ void cvt_tf32(const float4* __restrict__ in, float4* __restrict__ out, int n4) {
    int i = blockIdx.x * blockDim.x + threadIdx.x;
    if (i < n4) {
        float4 v = in[i];
        v.x = rndtf32(v.x); v.y = rndtf32(v.y);
        v.z = rndtf32(v.z); v.w = rndtf32(v.w);
        out[i] = v;
    }
}

// ---------------------------------------------------------------------------
// Shared GEMM mainloop pieces (validated R5/R6 mapping).
// CTA 128x128, BK=16, 256 threads (8 warps 2x4), warp tile 64x32, 3-stage cp.async.
// ---------------------------------------------------------------------------
#define TS 20
#define GSM_BYTES (3 * 2 * 128 * TS * 4)

struct GemmCore {
    uint32_t sbase;
    const uint32_t* sh;
    const float* A;
    const float* W;
    int K, bm, bn, tid;

    __device__ __forceinline__ void issue(int kt, int s) {
        const int k0 = kt << 4;
        const uint32_t so = (uint32_t)s * 5120u;
#pragma unroll
        for (int j = 0; j < 2; j++) {
            int idx = j * 256 + tid;
            int r = idx >> 2, c4 = idx & 3;
            uint32_t off = (so + (uint32_t)(r * TS + c4 * 4)) * 4u;
            cpasync16(sbase + off, A + (size_t)(bm + r) * K + k0 + c4 * 4);
            cpasync16(sbase + off + 2560u * 4u, W + (size_t)(bn + r) * K + k0 + c4 * 4);
        }
        asm volatile("cp.async.commit_group;" ::: "memory");
    }

    __device__ __forceinline__ void run(float acc[4][4][4], int wm, int wn, int g, int t) {
        const int NT = K >> 4;
        issue(0, 0);
        issue(1, 1);
        for (int kt = 0; kt < NT; kt++) {
            asm volatile("cp.async.wait_group %0;" :: "n"(1) : "memory");
            __syncthreads();
            if (kt + 2 < NT) issue(kt + 2, (kt + 2) % 3);
            const uint32_t* As = sh + (kt % 3) * 5120;
            const uint32_t* Ws = As + 2560;
#pragma unroll
            for (int kk = 0; kk < 2; kk++) {
                const int kc = kk * 8 + t;
                uint32_t af[4][4];
#pragma unroll
                for (int mi = 0; mi < 4; mi++) {
                    const int row = wm + mi * 16 + g;
                    af[mi][0] = As[(row    ) * TS + kc];
                    af[mi][1] = As[(row + 8) * TS + kc];
                    af[mi][2] = As[(row    ) * TS + kc + 4];
                    af[mi][3] = As[(row + 8) * TS + kc + 4];
                }
                uint32_t bf[4][2];
#pragma unroll
                for (int ni = 0; ni < 4; ni++) {
                    const int row = wn + ni * 8 + g;
                    bf[ni][0] = Ws[row * TS + kc];
                    bf[ni][1] = Ws[row * TS + kc + 4];
                }
#pragma unroll
                for (int mi = 0; mi < 4; mi++)
#pragma unroll
                    for (int ni = 0; ni < 4; ni++)
                        mma_tf32(acc[mi][ni], af[mi], bf[ni]);
            }
        }
    }
};

// Fused QKV projection: A[4096,2048] @ Wqkv[3072,2048]^T, column-routed epilogue.
__global__ __launch_bounds__(256) void gemm_qkv(
    const float* __restrict__ A, const float* __restrict__ Wc,
    const float* __restrict__ bq, const float* __restrict__ bk, const float* __restrict__ bv,
    float* __restrict__ q, float* __restrict__ k, float* __restrict__ v)
{
    extern __shared__ uint32_t sh[];
    const int tid = threadIdx.x;
    const int wid = tid >> 5;
    const int lane = tid & 31;
    const int g = lane >> 2, t = lane & 3;
    const int wm = (wid & 1) * 64, wn = (wid >> 1) * 32;
    const int bm = blockIdx.y * 128, bn = blockIdx.x * 128;

    GemmCore core{smem_u32(sh), sh, A, Wc, HIDDEN, bm, bn, tid};
    float acc[4][4][4] = {};
    core.run(acc, wm, wn, g, t);

    // Route by section (bn tile lies wholly in one section)
    float* out; const float* bias; int nout, cb;
    if (bn < HIDDEN)            { out = q; bias = bq; nout = HIDDEN; cb = bn; }
    else if (bn < HIDDEN + KVDIM) { out = k; bias = bk; nout = KVDIM; cb = bn - HIDDEN; }
    else                        { out = v; bias = bv; nout = KVDIM; cb = bn - HIDDEN - KVDIM; }

#pragma unroll
    for (int mi = 0; mi < 4; mi++) {
#pragma unroll
        for (int ni = 0; ni < 4; ni++) {
            const int col = cb + wn + ni * 8 + t * 2;
            const float bx = __ldg(bias + col);
            const float by = __ldg(bias + col + 1);
            const int rr0 = bm + wm + mi * 16 + g;
            float2 v0, v1;
            v0.x = rndtf32(acc[mi][ni][0] + bx); v0.y = rndtf32(acc[mi][ni][1] + by);
            v1.x = rndtf32(acc[mi][ni][2] + bx); v1.y = rndtf32(acc[mi][ni][3] + by);
            *(float2*)(out + (size_t)rr0 * nout + col) = v0;
            *(float2*)(out + (size_t)(rr0 + 8) * nout + col) = v1;
        }
    }
}

// O-projection: fp32 output, no rounding.
__global__ __launch_bounds__(256) void gemm_oproj(
    const float* __restrict__ A, const float* __restrict__ W,
    const float* __restrict__ bias, float* __restrict__ C)
{
    extern __shared__ uint32_t sh[];
    const int tid = threadIdx.x;
    const int wid = tid >> 5;
    const int lane = tid & 31;
    const int g = lane >> 2, t = lane & 3;
    const int wm = (wid & 1) * 64, wn = (wid >> 1) * 32;
    const int bm = blockIdx.y * 128, bn = blockIdx.x * 128;

    GemmCore core{smem_u32(sh), sh, A, W, HIDDEN, bm, bn, tid};
    float acc[4][4][4] = {};
    core.run(acc, wm, wn, g, t);

#pragma unroll
    for (int mi = 0; mi < 4; mi++) {
#pragma unroll
        for (int ni = 0; ni < 4; ni++) {
            const int col = bn + wn + ni * 8 + t * 2;
            const float bx = __ldg(bias + col);
            const float by = __ldg(bias + col + 1);
            const int rr0 = bm + wm + mi * 16 + g;
            float2 v0, v1;
            v0.x = acc[mi][ni][0] + bx; v0.y = acc[mi][ni][1] + by;
            v1.x = acc[mi][ni][2] + bx; v1.y = acc[mi][ni][3] + by;
            *(float2*)(C + (size_t)rr0 * HIDDEN + col) = v0;
            *(float2*)(C + (size_t)(rr0 + 8) * HIDDEN + col) = v1;
        }
    }
}

// ---------------------------------------------------------------------------
// Tensor-core flash attention (tf32 mma, fp32 accum).
// CTA = (128-query tile, head, batch). 256 threads = 8 warps x 16 q-rows.
// PV split into two 32-key halves so Ps is 16x36/warp -> 87KB smem -> 2 CTAs/SM.
// SMEM (words): Qs 128x68 | Ks 64x68 | Vs 64x72 | Ps 8x(16x36) = 89088 B.
// ---------------------------------------------------------------------------
#define ASM_BYTES ((128 * 68 + 64 * 68 + 64 * 72 + 8 * 16 * 36) * 4)

__global__ __launch_bounds__(256, 2) void attn_mma(
    const float* __restrict__ Q, const float* __restrict__ Kg,
    const float* __restrict__ Vg, float* __restrict__ O)
{
    extern __shared__ float sm[];
    float* Qs = sm;                       // stride 68
    float* Ks = Qs + 128 * 68;            // stride 68
    float* Vs = Ks + 64 * 68;             // stride 72
    float* Ps = Vs + 64 * 72;             // per-warp 16x36

    const int tid = threadIdx.x;
    const int wid = tid >> 5;
    const int lane = tid & 31;
    const int g = lane >> 2;
    const int t = lane & 3;
    const int qb = blockIdx.x;
    const int h  = blockIdx.y;
    const int b  = blockIdx.z;
    const int kvh = h >> 2;

    // Load Q tile (scale by 1/8: exact power of two, keeps tf32)
#pragma unroll
    for (int j = 0; j < 8; j++) {
        int idx = j * 256 + tid;
        int r = idx >> 4, c = (idx & 15) << 2;
        float4 v = *(const float4*)(Q + (size_t)(b * SEQ + qb * 128 + r) * HIDDEN + h * HDIM + c);
        v.x *= 0.125f; v.y *= 0.125f; v.z *= 0.125f; v.w *= 0.125f;
        *(float4*)&Qs[r * 68 + c] = v;
    }

    float* Pw = Ps + wid * 16 * 36;
    const int qr = wid * 16 + g;

    float acc_o[8][4] = {};
    float m0 = -1e30f, m1 = -1e30f, l0 = 0.f, l1 = 0.f;

    for (int jb = 0; jb < SEQ / 64; jb++) {
        __syncthreads();
        // Load K,V tiles
#pragma unroll
        for (int j = 0; j < 4; j++) {
            int idx = j * 256 + tid;
            int r = idx >> 4, c = (idx & 15) << 2;
            size_t gb = (size_t)(b * SEQ + jb * 64 + r) * KVDIM + kvh * HDIM + c;
            *(float4*)&Ks[r * 68 + c] = *(const float4*)(Kg + gb);
            *(float4*)&Vs[r * 72 + c] = *(const float4*)(Vg + gb);
        }
        __syncthreads();

        // S = Q K^T  (warp: 16 x 64)
        float acc_s[8][4] = {};
#pragma unroll
        for (int kk = 0; kk < 8; kk++) {
            const int kc = kk * 8 + t;
            uint32_t af[4];
            af[0] = __float_as_uint(Qs[qr * 68 + kc]);
            af[1] = __float_as_uint(Qs[(qr + 8) * 68 + kc]);
            af[2] = __float_as_uint(Qs[qr * 68 + kc + 4]);
            af[3] = __float_as_uint(Qs[(qr + 8) * 68 + kc + 4]);
#pragma unroll
            for (int ni = 0; ni < 8; ni++) {
                uint32_t bf[2];
                bf[0] = __float_as_uint(Ks[(ni * 8 + g) * 68 + kc]);
                bf[1] = __float_as_uint(Ks[(ni * 8 + g) * 68 + kc + 4]);
                mma_tf32(acc_s[ni], af, bf);
            }
        }

        // Fragment online softmax. Thread owns rows (qr, qr+8), 16 cols each.
        float mx0 = -1e30f, mx1 = -1e30f;
#pragma unroll
        for (int ni = 0; ni < 8; ni++) {
            mx0 = fmaxf(mx0, fmaxf(acc_s[ni][0], acc_s[ni][1]));
            mx1 = fmaxf(mx1, fmaxf(acc_s[ni][2], acc_s[ni][3]));
        }
        mx0 = fmaxf(mx0, __shfl_xor_sync(0xffffffffu, mx0, 1));
        mx0 = fmaxf(mx0, __shfl_xor_sync(0xffffffffu, mx0, 2));
        mx1 = fmaxf(mx1, __shfl_xor_sync(0xffffffffu, mx1, 1));
        mx1 = fmaxf(mx1, __shfl_xor_sync(0xffffffffu, mx1, 2));
        const float mn0 = fmaxf(m0, mx0);
        const float mn1 = fmaxf(m1, mx1);
        const float sf0 = __expf(m0 - mn0);
        const float sf1 = __expf(m1 - mn1);
        m0 = mn0; m1 = mn1;

        // Rescale accumulators before any PV accumulation of this tile
#pragma unroll
        for (int dn = 0; dn < 8; dn++) {
            acc_o[dn][0] *= sf0; acc_o[dn][1] *= sf0;
            acc_o[dn][2] *= sf1; acc_o[dn][3] *= sf1;
        }

        float rs0 = 0.f, rs1 = 0.f;
#pragma unroll
        for (int half = 0; half < 2; half++) {
            // Stage P[:, half*32 .. half*32+32) into per-warp tile (stride 36)
#pragma unroll
            for (int ni4 = 0; ni4 < 4; ni4++) {
                const int ni = half * 4 + ni4;
                float p0 = __expf(acc_s[ni][0] - mn0);
                float p1 = __expf(acc_s[ni][1] - mn0);
                float p2 = __expf(acc_s[ni][2] - mn1);
                float p3 = __expf(acc_s[ni][3] - mn1);
                rs0 += p0 + p1;
                rs1 += p2 + p3;
                float2 w0, w1;
                w0.x = rndtf32(p0); w0.y = rndtf32(p1);
                w1.x = rndtf32(p2); w1.y = rndtf32(p3);
                *(float2*)&Pw[g * 36 + ni4 * 8 + 2 * t] = w0;
                *(float2*)&Pw[(g + 8) * 36 + ni4 * 8 + 2 * t] = w1;
            }
            __syncwarp();

            // O += P_half V_half
#pragma unroll
            for (int kk = 0; kk < 4; kk++) {
                const int kc = kk * 8 + t;
                const int kv = half * 32 + kk * 8;
                uint32_t af[4];
                af[0] = __float_as_uint(Pw[g * 36 + kc]);
                af[1] = __float_as_uint(Pw[(g + 8) * 36 + kc]);
                af[2] = __float_as_uint(Pw[g * 36 + kc + 4]);
                af[3] = __float_as_uint(Pw[(g + 8) * 36 + kc + 4]);
#pragma unroll
                for (int dn = 0; dn < 8; dn++) {
                    uint32_t bf[2];
                    bf[0] = __float_as_uint(Vs[(kv + t) * 72 + dn * 8 + g]);
                    bf[1] = __float_as_uint(Vs[(kv + t + 4) * 72 + dn * 8 + g]);
                    mma_tf32(acc_o[dn], af, bf);
                }
            }
            __syncwarp();
        }

        rs0 += __shfl_xor_sync(0xffffffffu, rs0, 1);
        rs0 += __shfl_xor_sync(0xffffffffu, rs0, 2);
        rs1 += __shfl_xor_sync(0xffffffffu, rs1, 1);
        rs1 += __shfl_xor_sync(0xffffffffu, rs1, 2);
        l0 = l0 * sf0 + rs0;
        l1 = l1 * sf1 + rs1;
    }

    // Epilogue: normalize, round to tf32 (feeds O-proj mma), store.
    const float i0 = 1.f / l0;
    const float i1 = 1.f / l1;
    const int row0 = b * SEQ + qb * 128 + qr;
#pragma unroll
    for (int dn = 0; dn < 8; dn++) {
        const int col = h * HDIM + dn * 8 + 2 * t;
        float2 v0, v1;
        v0.x = rndtf32(acc_o[dn][0] * i0); v0.y = rndtf32(acc_o[dn][1] * i0);
        v1.x = rndtf32(acc_o[dn][2] * i1); v1.y = rndtf32(acc_o[dn][3] * i1);
        *(float2*)(O + (size_t)row0 * HIDDEN + col) = v0;
        *(float2*)(O + (size_t)(row0 + 8) * HIDDEN + col) = v1;
    }
}

// ---------------------------------------------------------------------------
extern "C" void kernel_launch(void* const* d_in, const int* in_sizes, int n_in,
                              void* d_out, int out_size)
{
    const float* x  = (const float*)d_in[0];
    const float* wq = (const float*)d_in[1];
    const float* bq = (const float*)d_in[2];
    const float* wk = (const float*)d_in[3];
    const float* bk = (const float*)d_in[4];
    const float* wv = (const float*)d_in[5];
    const float* bv = (const float*)d_in[6];
    const float* wo = (const float*)d_in[7];
    const float* bo = (const float*)d_in[8];
    float* out = (float*)d_out;

    float *q, *k, *v, *o, *xc, *wqkv, *woc;
    cudaGetSymbolAddress((void**)&q, g_q);
    cudaGetSymbolAddress((void**)&k, g_k);
    cudaGetSymbolAddress((void**)&v, g_v);
    cudaGetSymbolAddress((void**)&o, g_o);
    cudaGetSymbolAddress((void**)&xc, g_xc);
    cudaGetSymbolAddress((void**)&wqkv, g_wqkv);
    cudaGetSymbolAddress((void**)&woc, g_woc);

    cudaFuncSetAttribute(gemm_qkv,   cudaFuncAttributeMaxDynamicSharedMemorySize, GSM_BYTES);
    cudaFuncSetAttribute(gemm_oproj, cudaFuncAttributeMaxDynamicSharedMemorySize, GSM_BYTES);
    cudaFuncSetAttribute(attn_mma,   cudaFuncAttributeMaxDynamicSharedMemorySize, ASM_BYTES);

    // Pre-round inputs to tf32 (weights packed into combined QKV buffer)
    cvt_tf32<<<(MROWS * HIDDEN / 4 + 255) / 256, 256>>>((const float4*)x,  (float4*)xc,  MROWS * HIDDEN / 4);
    cvt_tf32<<<(HIDDEN * HIDDEN / 4 + 255) / 256, 256>>>((const float4*)wq, (float4*)(wqkv), HIDDEN * HIDDEN / 4);
    cvt_tf32<<<(KVDIM * HIDDEN / 4 + 255) / 256, 256>>>((const float4*)wk, (float4*)(wqkv + (size_t)HIDDEN * HIDDEN), KVDIM * HIDDEN / 4);
    cvt_tf32<<<(KVDIM * HIDDEN / 4 + 255) / 256, 256>>>((const float4*)wv, (float4*)(wqkv + (size_t)(HIDDEN + KVDIM) * HIDDEN), KVDIM * HIDDEN / 4);
    cvt_tf32<<<(HIDDEN * HIDDEN / 4 + 255) / 256, 256>>>((const float4*)wo, (float4*)woc, HIDDEN * HIDDEN / 4);

    // Fused Q/K/V projection (outputs tf32-rounded: they feed attention mma)
    gemm_qkv<<<dim3(NQKV / 128, MROWS / 128), 256, GSM_BYTES>>>(xc, wqkv, bq, bk, bv, q, k, v);

    // Attention (tensor core, 2 CTAs/SM)
    attn_mma<<<dim3(SEQ / 128, NHEADS, BATCH), 256, ASM_BYTES>>>(q, k, v, o);

    // Output projection (fp32 output)
    gemm_oproj<<<dim3(HIDDEN / 128, MROWS / 128), 256, GSM_BYTES>>>(o, woc, bo, out);
}

// round 9
// speedup vs baseline: 6.9984x; 1.8254x over previous
#include <cuda_runtime.h>
#include <cuda_fp16.h>
#include <cstdint>

// Problem constants
#define BATCH 2
#define SEQ 2048
#define HIDDEN 2048
#define NHEADS 32
#define NKV 8
#define HDIM 64
#define KVDIM 512
#define MROWS (BATCH * SEQ)        // 4096
#define NQKV (HIDDEN + 2 * KVDIM)  // 3072

// Scratch (allocation-free rule: __device__ globals), all fp16
__device__ __align__(16) __half g_xh[MROWS * HIDDEN];
__device__ __align__(16) __half g_wqkvh[NQKV * HIDDEN];
__device__ __align__(16) __half g_woh[HIDDEN * HIDDEN];
__device__ __align__(16) __half g_qh[MROWS * HIDDEN];
__device__ __align__(16) __half g_kh[MROWS * KVDIM];
__device__ __align__(16) __half g_vt[BATCH * NKV * HDIM * SEQ];  // [b,kvh,d][s]
__device__ __align__(16) __half g_oh[MROWS * HIDDEN];

__device__ __forceinline__ void mma_f16(float* d, const uint32_t* a, const uint32_t* b) {
    asm volatile(
        "mma.sync.aligned.m16n8k16.row.col.f32.f16.f16.f32 "
        "{%0,%1,%2,%3}, {%4,%5,%6,%7}, {%8,%9}, {%0,%1,%2,%3};"
        : "+f"(d[0]), "+f"(d[1]), "+f"(d[2]), "+f"(d[3])
        : "r"(a[0]), "r"(a[1]), "r"(a[2]), "r"(a[3]), "r"(b[0]), "r"(b[1]));
}

__device__ __forceinline__ uint32_t smem_u32(const void* p) {
    uint32_t a;
    asm("{ .reg .u64 t; cvta.to.shared.u64 t, %1; cvt.u32.u64 %0, t; }" : "=r"(a) : "l"(p));
    return a;
}

__device__ __forceinline__ void cpasync16(uint32_t dst, const void* src) {
    asm volatile("cp.async.ca.shared.global [%0], [%1], 16;" :: "r"(dst), "l"(src));
}

// ---------------------------------------------------------------------------
// fp32 -> fp16 conversion
// ---------------------------------------------------------------------------
__global__ void cvt_f16(const float4* __restrict__ in, uint2* __restrict__ out, int n4) {
    int i = blockIdx.x * blockDim.x + threadIdx.x;
    if (i < n4) {
        float4 v = in[i];
        __half2 h0 = __floats2half2_rn(v.x, v.y);
        __half2 h1 = __floats2half2_rn(v.z, v.w);
        uint2 o;
        o.x = *(uint32_t*)&h0;
        o.y = *(uint32_t*)&h1;
        out[i] = o;
    }
}

// ---------------------------------------------------------------------------
// fp16 GEMM core: C[M,N] = A[M,K] @ W[N,K]^T  (A,W fp16, fp32 accum)
// CTA 128x128, BK=32 (16 uint32/row), 256 threads (8 warps 2x4), warp 64x32.
// SMEM stride 20 uint32 (validated conflict-free). 3-stage cp.async.
// ---------------------------------------------------------------------------
#define TS 20
#define GSM_BYTES (3 * 2 * 128 * TS * 4)

struct GemmCore {
    uint32_t sbase;
    const uint32_t* sh;
    const uint32_t* A;   // packed half2, row stride K2
    const uint32_t* W;
    int K2;              // K/2 (uint32 per row)
    int bm, bn, tid;

    __device__ __forceinline__ void issue(int kt, int s) {
        const int k0u = kt << 4;  // 16 uint32 per BK=32
        const uint32_t so = (uint32_t)s * 5120u;
#pragma unroll
        for (int j = 0; j < 2; j++) {
            int idx = j * 256 + tid;
            int r = idx >> 2, c4 = idx & 3;
            uint32_t off = (so + (uint32_t)(r * TS + c4 * 4)) * 4u;
            cpasync16(sbase + off, A + (size_t)(bm + r) * K2 + k0u + c4 * 4);
            cpasync16(sbase + off + 2560u * 4u, W + (size_t)(bn + r) * K2 + k0u + c4 * 4);
        }
        asm volatile("cp.async.commit_group;" ::: "memory");
    }

    __device__ __forceinline__ void run(float acc[4][4][4], int wm, int wn, int g, int t) {
        const int NT = K2 >> 4;
        issue(0, 0);
        issue(1, 1);
        for (int kt = 0; kt < NT; kt++) {
            asm volatile("cp.async.wait_group %0;" :: "n"(1) : "memory");
            __syncthreads();
            if (kt + 2 < NT) issue(kt + 2, (kt + 2) % 3);
            const uint32_t* As = sh + (kt % 3) * 5120;
            const uint32_t* Ws = As + 2560;
#pragma unroll
            for (int kk = 0; kk < 2; kk++) {
                const int kc = kk * 8 + t;
                uint32_t af[4][4];
#pragma unroll
                for (int mi = 0; mi < 4; mi++) {
                    const int row = wm + mi * 16 + g;
                    af[mi][0] = As[(row    ) * TS + kc];
                    af[mi][1] = As[(row + 8) * TS + kc];
                    af[mi][2] = As[(row    ) * TS + kc + 4];
                    af[mi][3] = As[(row + 8) * TS + kc + 4];
                }
                uint32_t bf[4][2];
#pragma unroll
                for (int ni = 0; ni < 4; ni++) {
                    const int row = wn + ni * 8 + g;
                    bf[ni][0] = Ws[row * TS + kc];
                    bf[ni][1] = Ws[row * TS + kc + 4];
                }
#pragma unroll
                for (int mi = 0; mi < 4; mi++)
#pragma unroll
                    for (int ni = 0; ni < 4; ni++)
                        mma_f16(acc[mi][ni], af[mi], bf[ni]);
            }
        }
    }
};

// Fused QKV projection; q/k written fp16 row-major, v written fp16 TRANSPOSED.
__global__ __launch_bounds__(256) void gemm_qkv(
    const uint32_t* __restrict__ A, const uint32_t* __restrict__ Wc,
    const float* __restrict__ bq, const float* __restrict__ bk, const float* __restrict__ bv,
    uint32_t* __restrict__ q, uint32_t* __restrict__ k, __half* __restrict__ vt)
{
    extern __shared__ uint32_t sh[];
    const int tid = threadIdx.x;
    const int wid = tid >> 5;
    const int lane = tid & 31;
    const int g = lane >> 2, t = lane & 3;
    const int wm = (wid & 1) * 64, wn = (wid >> 1) * 32;
    const int bm = blockIdx.y * 128, bn = blockIdx.x * 128;

    GemmCore core{smem_u32(sh), sh, A, Wc, HIDDEN / 2, bm, bn, tid};
    float acc[4][4][4] = {};
    core.run(acc, wm, wn, g, t);

    if (bn < HIDDEN) {
        // Q section: [row][2048] fp16
        const float* bias = bq;
#pragma unroll
        for (int mi = 0; mi < 4; mi++)
#pragma unroll
            for (int ni = 0; ni < 4; ni++) {
                const int col = bn + wn + ni * 8 + 2 * t;
                const float bx = __ldg(bias + col);
                const float by = __ldg(bias + col + 1);
                const int rr0 = bm + wm + mi * 16 + g;
                __half2 h0 = __floats2half2_rn(acc[mi][ni][0] + bx, acc[mi][ni][1] + by);
                __half2 h1 = __floats2half2_rn(acc[mi][ni][2] + bx, acc[mi][ni][3] + by);
                q[(size_t)rr0 * (HIDDEN / 2) + (col >> 1)] = *(uint32_t*)&h0;
                q[(size_t)(rr0 + 8) * (HIDDEN / 2) + (col >> 1)] = *(uint32_t*)&h1;
            }
    } else if (bn < HIDDEN + KVDIM) {
        // K section: [row][512] fp16
        const float* bias = bk;
        const int cb = bn - HIDDEN;
#pragma unroll
        for (int mi = 0; mi < 4; mi++)
#pragma unroll
            for (int ni = 0; ni < 4; ni++) {
                const int col = cb + wn + ni * 8 + 2 * t;
                const float bx = __ldg(bias + col);
                const float by = __ldg(bias + col + 1);
                const int rr0 = bm + wm + mi * 16 + g;
                __half2 h0 = __floats2half2_rn(acc[mi][ni][0] + bx, acc[mi][ni][1] + by);
                __half2 h1 = __floats2half2_rn(acc[mi][ni][2] + bx, acc[mi][ni][3] + by);
                k[(size_t)rr0 * (KVDIM / 2) + (col >> 1)] = *(uint32_t*)&h0;
                k[(size_t)(rr0 + 8) * (KVDIM / 2) + (col >> 1)] = *(uint32_t*)&h1;
            }
    } else {
        // V section: transposed store vt[(b*NKV+kvh)*HDIM + d][s]
        const float* bias = bv;
        const int cb = bn - HIDDEN - KVDIM;
#pragma unroll
        for (int mi = 0; mi < 4; mi++)
#pragma unroll
            for (int ni = 0; ni < 4; ni++) {
                const int col = cb + wn + ni * 8 + 2 * t;   // d index (even)
                const float bx = __ldg(bias + col);
                const float by = __ldg(bias + col + 1);
#pragma unroll
                for (int rr = 0; rr < 2; rr++) {
                    const int row = bm + wm + mi * 16 + g + rr * 8;
                    const int bb = row >> 11;          // batch
                    const int s  = row & 2047;         // seq pos
                    const float v0 = acc[mi][ni][rr * 2 + 0] + bx;
                    const float v1 = acc[mi][ni][rr * 2 + 1] + by;
                    const size_t base = ((size_t)(bb * NKV + (col >> 6)) * HDIM);
                    vt[(base + (col & 63)) * SEQ + s]     = __float2half_rn(v0);
                    vt[(base + (col & 63) + 1) * SEQ + s] = __float2half_rn(v1);
                }
            }
    }
}

// O-projection: fp16 inputs, fp32 output + bias.
__global__ __launch_bounds__(256) void gemm_oproj(
    const uint32_t* __restrict__ A, const uint32_t* __restrict__ W,
    const float* __restrict__ bias, float* __restrict__ C)
{
    extern __shared__ uint32_t sh[];
    const int tid = threadIdx.x;
    const int wid = tid >> 5;
    const int lane = tid & 31;
    const int g = lane >> 2, t = lane & 3;
    const int wm = (wid & 1) * 64, wn = (wid >> 1) * 32;
    const int bm = blockIdx.y * 128, bn = blockIdx.x * 128;

    GemmCore core{smem_u32(sh), sh, A, W, HIDDEN / 2, bm, bn, tid};
    float acc[4][4][4] = {};
    core.run(acc, wm, wn, g, t);

#pragma unroll
    for (int mi = 0; mi < 4; mi++)
#pragma unroll
        for (int ni = 0; ni < 4; ni++) {
            const int col = bn + wn + ni * 8 + 2 * t;
            const float bx = __ldg(bias + col);
            const float by = __ldg(bias + col + 1);
            const int rr0 = bm + wm + mi * 16 + g;
            float2 v0, v1;
            v0.x = acc[mi][ni][0] + bx; v0.y = acc[mi][ni][1] + by;
            v1.x = acc[mi][ni][2] + bx; v1.y = acc[mi][ni][3] + by;
            *(float2*)(C + (size_t)rr0 * HIDDEN + col) = v0;
            *(float2*)(C + (size_t)(rr0 + 8) * HIDDEN + col) = v1;
        }
}

// ---------------------------------------------------------------------------
// fp16 tensor-core flash attention (fp32 accum/softmax).
// CTA = (128-query tile, head, batch). 256 threads = 8 warps x 16 q-rows.
// SMEM (uint32, stride 36): Qs 128x36 | Ks 64x36 | Vt 64x36 | Ps 8x16x36
//   = 55296 B -> 2 CTAs/SM. All fragment access patterns conflict-free (4g+t).
// ---------------------------------------------------------------------------
#define ASM_BYTES ((128 * 36 + 64 * 36 + 64 * 36 + 8 * 16 * 36) * 4)

__global__ __launch_bounds__(256, 2) void attn_mma(
    const uint32_t* __restrict__ Qh, const uint32_t* __restrict__ Kh,
    const uint32_t* __restrict__ Vth, uint32_t* __restrict__ Oh)
{
    extern __shared__ uint32_t sm32[];
    uint32_t* Qs = sm32;                  // [128][36] (q-row x d-pair)
    uint32_t* Ks = Qs + 128 * 36;         // [64][36]  (key x d-pair)
    uint32_t* Vt = Ks + 64 * 36;          // [64][36]  (d x key-pair)
    uint32_t* Ps = Vt + 64 * 36;          // per-warp [16][36] (q-row x key-pair)

    const int tid = threadIdx.x;
    const int wid = tid >> 5;
    const int lane = tid & 31;
    const int g = lane >> 2;
    const int t = lane & 3;
    const int qb = blockIdx.x;
    const int h  = blockIdx.y;
    const int b  = blockIdx.z;
    const int kvh = h >> 2;

    // Load Q tile, scale by 1/8 (exact in fp16)
    {
        const __half2 sc = __float2half2_rn(0.125f);
        const uint32_t* src = Qh + (size_t)(b * SEQ + qb * 128) * (HIDDEN / 2) + h * (HDIM / 2);
#pragma unroll
        for (int j = 0; j < 4; j++) {
            int idx = j * 256 + tid;
            int r = idx >> 3, c = (idx & 7) * 4;
            uint4 v = *(const uint4*)(src + (size_t)r * (HIDDEN / 2) + c);
            __half2* hp = (__half2*)&v;
            hp[0] = __hmul2(hp[0], sc); hp[1] = __hmul2(hp[1], sc);
            hp[2] = __hmul2(hp[2], sc); hp[3] = __hmul2(hp[3], sc);
            uint32_t* dst = &Qs[r * 36 + c];
            dst[0] = v.x; dst[1] = v.y; dst[2] = v.z; dst[3] = v.w;
        }
    }

    uint32_t* Pw = Ps + wid * 16 * 36;
    const int qr = wid * 16 + g;

    float acc_o[8][4] = {};
    float m0 = -1e30f, m1 = -1e30f, l0 = 0.f, l1 = 0.f;

    const uint32_t* Kbase  = Kh + (size_t)(b * SEQ) * (KVDIM / 2) + kvh * (HDIM / 2);
    const uint32_t* Vtbase = Vth + (size_t)((b * NKV + kvh) * HDIM) * (SEQ / 2);

    for (int jb = 0; jb < SEQ / 64; jb++) {
        __syncthreads();
        // K tile: 64 keys x 32 d-pairs ; Vt tile: 64 d x 32 key-pairs
#pragma unroll
        for (int j = 0; j < 2; j++) {
            int idx = j * 256 + tid;
            int r = idx >> 3, c = (idx & 7) * 4;
            uint4 kv = *(const uint4*)(Kbase + (size_t)(jb * 64 + r) * (KVDIM / 2) + c);
            uint32_t* kd = &Ks[r * 36 + c];
            kd[0] = kv.x; kd[1] = kv.y; kd[2] = kv.z; kd[3] = kv.w;
            uint4 vv = *(const uint4*)(Vtbase + (size_t)r * (SEQ / 2) + jb * 32 + c);
            uint32_t* vd = &Vt[r * 36 + c];
            vd[0] = vv.x; vd[1] = vv.y; vd[2] = vv.z; vd[3] = vv.w;
        }
        __syncthreads();

        // S = Q K^T : 4 k16 steps over D=64
        float acc_s[8][4] = {};
#pragma unroll
        for (int kk = 0; kk < 4; kk++) {
            const int kc = kk * 8 + t;
            uint32_t af[4];
            af[0] = Qs[qr * 36 + kc];
            af[1] = Qs[(qr + 8) * 36 + kc];
            af[2] = Qs[qr * 36 + kc + 4];
            af[3] = Qs[(qr + 8) * 36 + kc + 4];
#pragma unroll
            for (int ni = 0; ni < 8; ni++) {
                uint32_t bf[2];
                bf[0] = Ks[(ni * 8 + g) * 36 + kc];
                bf[1] = Ks[(ni * 8 + g) * 36 + kc + 4];
                mma_f16(acc_s[ni], af, bf);
            }
        }

        // Fragment online softmax (rows qr, qr+8; 16 cols/thread)
        float mx0 = -1e30f, mx1 = -1e30f;
#pragma unroll
        for (int ni = 0; ni < 8; ni++) {
            mx0 = fmaxf(mx0, fmaxf(acc_s[ni][0], acc_s[ni][1]));
            mx1 = fmaxf(mx1, fmaxf(acc_s[ni][2], acc_s[ni][3]));
        }
        mx0 = fmaxf(mx0, __shfl_xor_sync(0xffffffffu, mx0, 1));
        mx0 = fmaxf(mx0, __shfl_xor_sync(0xffffffffu, mx0, 2));
        mx1 = fmaxf(mx1, __shfl_xor_sync(0xffffffffu, mx1, 1));
        mx1 = fmaxf(mx1, __shfl_xor_sync(0xffffffffu, mx1, 2));
        const float mn0 = fmaxf(m0, mx0);
        const float mn1 = fmaxf(m1, mx1);
        const float sf0 = __expf(m0 - mn0);
        const float sf1 = __expf(m1 - mn1);
        m0 = mn0; m1 = mn1;

#pragma unroll
        for (int dn = 0; dn < 8; dn++) {
            acc_o[dn][0] *= sf0; acc_o[dn][1] *= sf0;
            acc_o[dn][2] *= sf1; acc_o[dn][3] *= sf1;
        }

        // P = exp(S - m), staged fp16 into per-warp tile
        float rs0 = 0.f, rs1 = 0.f;
#pragma unroll
        for (int ni = 0; ni < 8; ni++) {
            float p0 = __expf(acc_s[ni][0] - mn0);
            float p1 = __expf(acc_s[ni][1] - mn0);
            float p2 = __expf(acc_s[ni][2] - mn1);
            float p3 = __expf(acc_s[ni][3] - mn1);
            rs0 += p0 + p1;
            rs1 += p2 + p3;
            __half2 w0 = __floats2half2_rn(p0, p1);
            __half2 w1 = __floats2half2_rn(p2, p3);
            Pw[g * 36 + ni * 4 + t] = *(uint32_t*)&w0;
            Pw[(g + 8) * 36 + ni * 4 + t] = *(uint32_t*)&w1;
        }
        rs0 += __shfl_xor_sync(0xffffffffu, rs0, 1);
        rs0 += __shfl_xor_sync(0xffffffffu, rs0, 2);
        rs1 += __shfl_xor_sync(0xffffffffu, rs1, 1);
        rs1 += __shfl_xor_sync(0xffffffffu, rs1, 2);
        l0 = l0 * sf0 + rs0;
        l1 = l1 * sf1 + rs1;
        __syncwarp();

        // O += P V : 4 k16 steps over 64 keys
#pragma unroll
        for (int kk = 0; kk < 4; kk++) {
            const int kc = kk * 8 + t;
            uint32_t af[4];
            af[0] = Pw[g * 36 + kc];
            af[1] = Pw[(g + 8) * 36 + kc];
            af[2] = Pw[g * 36 + kc + 4];
            af[3] = Pw[(g + 8) * 36 + kc + 4];
#pragma unroll
            for (int dn = 0; dn < 8; dn++) {
                uint32_t bf[2];
                bf[0] = Vt[(dn * 8 + g) * 36 + kc];
                bf[1] = Vt[(dn * 8 + g) * 36 + kc + 4];
                mma_f16(acc_o[dn], af, bf);
            }
        }
        __syncwarp();
    }

    // Epilogue: normalize, store fp16 (feeds O-proj mma)
    const float i0 = 1.f / l0;
    const float i1 = 1.f / l1;
    const int row0 = b * SEQ + qb * 128 + qr;
#pragma unroll
    for (int dn = 0; dn < 8; dn++) {
        const int cp = h * (HDIM / 2) + dn * 4 + t;   // uint32 column
        __half2 h0 = __floats2half2_rn(acc_o[dn][0] * i0, acc_o[dn][1] * i0);
        __half2 h1 = __floats2half2_rn(acc_o[dn][2] * i1, acc_o[dn][3] * i1);
        Oh[(size_t)row0 * (HIDDEN / 2) + cp] = *(uint32_t*)&h0;
        Oh[(size_t)(row0 + 8) * (HIDDEN / 2) + cp] = *(uint32_t*)&h1;
    }
}

// ---------------------------------------------------------------------------
extern "C" void kernel_launch(void* const* d_in, const int* in_sizes, int n_in,
                              void* d_out, int out_size)
{
    const float* x  = (const float*)d_in[0];
    const float* wq = (const float*)d_in[1];
    const float* bq = (const float*)d_in[2];
    const float* wk = (const float*)d_in[3];
    const float* bk = (const float*)d_in[4];
    const float* wv = (const float*)d_in[5];
    const float* bv = (const float*)d_in[6];
    const float* wo = (const float*)d_in[7];
    const float* bo = (const float*)d_in[8];
    float* out = (float*)d_out;

    __half *xh, *wqkvh, *woh, *qh, *kh, *vt, *oh;
    cudaGetSymbolAddress((void**)&xh, g_xh);
    cudaGetSymbolAddress((void**)&wqkvh, g_wqkvh);
    cudaGetSymbolAddress((void**)&woh, g_woh);
    cudaGetSymbolAddress((void**)&qh, g_qh);
    cudaGetSymbolAddress((void**)&kh, g_kh);
    cudaGetSymbolAddress((void**)&vt, g_vt);
    cudaGetSymbolAddress((void**)&oh, g_oh);

    cudaFuncSetAttribute(gemm_qkv,   cudaFuncAttributeMaxDynamicSharedMemorySize, GSM_BYTES);
    cudaFuncSetAttribute(gemm_oproj, cudaFuncAttributeMaxDynamicSharedMemorySize, GSM_BYTES);
    cudaFuncSetAttribute(attn_mma,   cudaFuncAttributeMaxDynamicSharedMemorySize, ASM_BYTES);

    // fp32 -> fp16 conversions (weights packed into combined QKV buffer)
    cvt_f16<<<(MROWS * HIDDEN / 4 + 255) / 256, 256>>>((const float4*)x,  (uint2*)xh, MROWS * HIDDEN / 4);
    cvt_f16<<<(HIDDEN * HIDDEN / 4 + 255) / 256, 256>>>((const float4*)wq, (uint2*)wqkvh, HIDDEN * HIDDEN / 4);
    cvt_f16<<<(KVDIM * HIDDEN / 4 + 255) / 256, 256>>>((const float4*)wk, (uint2*)(wqkvh + (size_t)HIDDEN * HIDDEN), KVDIM * HIDDEN / 4);
    cvt_f16<<<(KVDIM * HIDDEN / 4 + 255) / 256, 256>>>((const float4*)wv, (uint2*)(wqkvh + (size_t)(HIDDEN + KVDIM) * HIDDEN), KVDIM * HIDDEN / 4);
    cvt_f16<<<(HIDDEN * HIDDEN / 4 + 255) / 256, 256>>>((const float4*)wo, (uint2*)woh, HIDDEN * HIDDEN / 4);

    // Fused Q/K/V projection (fp16 outputs; V transposed)
    gemm_qkv<<<dim3(NQKV / 128, MROWS / 128), 256, GSM_BYTES>>>(
        (const uint32_t*)xh, (const uint32_t*)wqkvh, bq, bk, bv,
        (uint32_t*)qh, (uint32_t*)kh, vt);

    // Attention (fp16 tensor core, 2 CTAs/SM)
    attn_mma<<<dim3(SEQ / 128, NHEADS, BATCH), 256, ASM_BYTES>>>(
        (const uint32_t*)qh, (const uint32_t*)kh, (const uint32_t*)vt, (uint32_t*)oh);

    // Output projection (fp32 output + bias)
    gemm_oproj<<<dim3(HIDDEN / 128, MROWS / 128), 256, GSM_BYTES>>>(
        (const uint32_t*)oh, (const uint32_t*)woh, bo, out);
}

// round 10
// speedup vs baseline: 7.5648x; 1.0809x over previous
#include <cuda_runtime.h>
#include <cuda_fp16.h>
#include <cstdint>

// Problem constants
#define BATCH 2
#define SEQ 2048
#define HIDDEN 2048
#define NHEADS 32
#define NKV 8
#define HDIM 64
#define KVDIM 512
#define MROWS (BATCH * SEQ)        // 4096
#define NQKV (HIDDEN + 2 * KVDIM)  // 3072

// Scratch (allocation-free rule: __device__ globals), all fp16
__device__ __align__(16) __half g_xh[MROWS * HIDDEN];
__device__ __align__(16) __half g_wqkvh[NQKV * HIDDEN];
__device__ __align__(16) __half g_woh[HIDDEN * HIDDEN];
__device__ __align__(16) __half g_qh[MROWS * HIDDEN];
__device__ __align__(16) __half g_kh[MROWS * KVDIM];
__device__ __align__(16) __half g_vt[BATCH * NKV * HDIM * SEQ];  // [b,kvh,d][s]
__device__ __align__(16) __half g_oh[MROWS * HIDDEN];

__device__ __forceinline__ void mma_f16(float* d, const uint32_t* a, const uint32_t* b) {
    asm volatile(
        "mma.sync.aligned.m16n8k16.row.col.f32.f16.f16.f32 "
        "{%0,%1,%2,%3}, {%4,%5,%6,%7}, {%8,%9}, {%0,%1,%2,%3};"
        : "+f"(d[0]), "+f"(d[1]), "+f"(d[2]), "+f"(d[3])
        : "r"(a[0]), "r"(a[1]), "r"(a[2]), "r"(a[3]), "r"(b[0]), "r"(b[1]));
}

__device__ __forceinline__ uint32_t smem_u32(const void* p) {
    uint32_t a;
    asm("{ .reg .u64 t; cvta.to.shared.u64 t, %1; cvt.u32.u64 %0, t; }" : "=r"(a) : "l"(p));
    return a;
}

__device__ __forceinline__ void cpasync16(uint32_t dst, const void* src) {
    asm volatile("cp.async.ca.shared.global [%0], [%1], 16;" :: "r"(dst), "l"(src));
}

// ---------------------------------------------------------------------------
// fp32 -> fp16 conversion
// ---------------------------------------------------------------------------
__global__ void cvt_f16(const float4* __restrict__ in, uint2* __restrict__ out, int n4) {
    int i = blockIdx.x * blockDim.x + threadIdx.x;
    if (i < n4) {
        float4 v = in[i];
        __half2 h0 = __floats2half2_rn(v.x, v.y);
        __half2 h1 = __floats2half2_rn(v.z, v.w);
        uint2 o;
        o.x = *(uint32_t*)&h0;
        o.y = *(uint32_t*)&h1;
        out[i] = o;
    }
}

// ---------------------------------------------------------------------------
// fp16 GEMM core (validated R9): C[M,N] = A[M,K] @ W[N,K]^T, fp32 accum.
// CTA 128x128, BK=32 (16 uint32/row), 256 threads (8 warps 2x4), warp 64x32.
// ---------------------------------------------------------------------------
#define TS 20
#define GSM_BYTES (3 * 2 * 128 * TS * 4)

struct GemmCore {
    uint32_t sbase;
    const uint32_t* sh;
    const uint32_t* A;
    const uint32_t* W;
    int K2;
    int bm, bn, tid;

    __device__ __forceinline__ void issue(int kt, int s) {
        const int k0u = kt << 4;
        const uint32_t so = (uint32_t)s * 5120u;
#pragma unroll
        for (int j = 0; j < 2; j++) {
            int idx = j * 256 + tid;
            int r = idx >> 2, c4 = idx & 3;
            uint32_t off = (so + (uint32_t)(r * TS + c4 * 4)) * 4u;
            cpasync16(sbase + off, A + (size_t)(bm + r) * K2 + k0u + c4 * 4);
            cpasync16(sbase + off + 2560u * 4u, W + (size_t)(bn + r) * K2 + k0u + c4 * 4);
        }
        asm volatile("cp.async.commit_group;" ::: "memory");
    }

    __device__ __forceinline__ void run(float acc[4][4][4], int wm, int wn, int g, int t) {
        const int NT = K2 >> 4;
        issue(0, 0);
        issue(1, 1);
        for (int kt = 0; kt < NT; kt++) {
            asm volatile("cp.async.wait_group %0;" :: "n"(1) : "memory");
            __syncthreads();
            if (kt + 2 < NT) issue(kt + 2, (kt + 2) % 3);
            const uint32_t* As = sh + (kt % 3) * 5120;
            const uint32_t* Ws = As + 2560;
#pragma unroll
            for (int kk = 0; kk < 2; kk++) {
                const int kc = kk * 8 + t;
                uint32_t af[4][4];
#pragma unroll
                for (int mi = 0; mi < 4; mi++) {
                    const int row = wm + mi * 16 + g;
                    af[mi][0] = As[(row    ) * TS + kc];
                    af[mi][1] = As[(row + 8) * TS + kc];
                    af[mi][2] = As[(row    ) * TS + kc + 4];
                    af[mi][3] = As[(row + 8) * TS + kc + 4];
                }
                uint32_t bf[4][2];
#pragma unroll
                for (int ni = 0; ni < 4; ni++) {
                    const int row = wn + ni * 8 + g;
                    bf[ni][0] = Ws[row * TS + kc];
                    bf[ni][1] = Ws[row * TS + kc + 4];
                }
#pragma unroll
                for (int mi = 0; mi < 4; mi++)
#pragma unroll
                    for (int ni = 0; ni < 4; ni++)
                        mma_f16(acc[mi][ni], af[mi], bf[ni]);
            }
        }
    }
};

// Fused QKV projection; q/k written fp16 row-major, v written fp16 TRANSPOSED.
__global__ __launch_bounds__(256) void gemm_qkv(
    const uint32_t* __restrict__ A, const uint32_t* __restrict__ Wc,
    const float* __restrict__ bq, const float* __restrict__ bk, const float* __restrict__ bv,
    uint32_t* __restrict__ q, uint32_t* __restrict__ k, __half* __restrict__ vt)
{
    extern __shared__ uint32_t sh[];
    const int tid = threadIdx.x;
    const int wid = tid >> 5;
    const int lane = tid & 31;
    const int g = lane >> 2, t = lane & 3;
    const int wm = (wid & 1) * 64, wn = (wid >> 1) * 32;
    const int bm = blockIdx.y * 128, bn = blockIdx.x * 128;

    GemmCore core{smem_u32(sh), sh, A, Wc, HIDDEN / 2, bm, bn, tid};
    float acc[4][4][4] = {};
    core.run(acc, wm, wn, g, t);

    if (bn < HIDDEN) {
        const float* bias = bq;
#pragma unroll
        for (int mi = 0; mi < 4; mi++)
#pragma unroll
            for (int ni = 0; ni < 4; ni++) {
                const int col = bn + wn + ni * 8 + 2 * t;
                const float bx = __ldg(bias + col);
                const float by = __ldg(bias + col + 1);
                const int rr0 = bm + wm + mi * 16 + g;
                __half2 h0 = __floats2half2_rn(acc[mi][ni][0] + bx, acc[mi][ni][1] + by);
                __half2 h1 = __floats2half2_rn(acc[mi][ni][2] + bx, acc[mi][ni][3] + by);
                q[(size_t)rr0 * (HIDDEN / 2) + (col >> 1)] = *(uint32_t*)&h0;
                q[(size_t)(rr0 + 8) * (HIDDEN / 2) + (col >> 1)] = *(uint32_t*)&h1;
            }
    } else if (bn < HIDDEN + KVDIM) {
        const float* bias = bk;
        const int cb = bn - HIDDEN;
#pragma unroll
        for (int mi = 0; mi < 4; mi++)
#pragma unroll
            for (int ni = 0; ni < 4; ni++) {
                const int col = cb + wn + ni * 8 + 2 * t;
                const float bx = __ldg(bias + col);
                const float by = __ldg(bias + col + 1);
                const int rr0 = bm + wm + mi * 16 + g;
                __half2 h0 = __floats2half2_rn(acc[mi][ni][0] + bx, acc[mi][ni][1] + by);
                __half2 h1 = __floats2half2_rn(acc[mi][ni][2] + bx, acc[mi][ni][3] + by);
                k[(size_t)rr0 * (KVDIM / 2) + (col >> 1)] = *(uint32_t*)&h0;
                k[(size_t)(rr0 + 8) * (KVDIM / 2) + (col >> 1)] = *(uint32_t*)&h1;
            }
    } else {
        const float* bias = bv;
        const int cb = bn - HIDDEN - KVDIM;
#pragma unroll
        for (int mi = 0; mi < 4; mi++)
#pragma unroll
            for (int ni = 0; ni < 4; ni++) {
                const int col = cb + wn + ni * 8 + 2 * t;   // d index (even)
                const float bx = __ldg(bias + col);
                const float by = __ldg(bias + col + 1);
#pragma unroll
                for (int rr = 0; rr < 2; rr++) {
                    const int row = bm + wm + mi * 16 + g + rr * 8;
                    const int bb = row >> 11;
                    const int s  = row & 2047;
                    const float v0 = acc[mi][ni][rr * 2 + 0] + bx;
                    const float v1 = acc[mi][ni][rr * 2 + 1] + by;
                    const size_t base = ((size_t)(bb * NKV + (col >> 6)) * HDIM);
                    vt[(base + (col & 63)) * SEQ + s]     = __float2half_rn(v0);
                    vt[(base + (col & 63) + 1) * SEQ + s] = __float2half_rn(v1);
                }
            }
    }
}

// O-projection: fp16 inputs, fp32 output + bias.
__global__ __launch_bounds__(256) void gemm_oproj(
    const uint32_t* __restrict__ A, const uint32_t* __restrict__ W,
    const float* __restrict__ bias, float* __restrict__ C)
{
    extern __shared__ uint32_t sh[];
    const int tid = threadIdx.x;
    const int wid = tid >> 5;
    const int lane = tid & 31;
    const int g = lane >> 2, t = lane & 3;
    const int wm = (wid & 1) * 64, wn = (wid >> 1) * 32;
    const int bm = blockIdx.y * 128, bn = blockIdx.x * 128;

    GemmCore core{smem_u32(sh), sh, A, W, HIDDEN / 2, bm, bn, tid};
    float acc[4][4][4] = {};
    core.run(acc, wm, wn, g, t);

#pragma unroll
    for (int mi = 0; mi < 4; mi++)
#pragma unroll
        for (int ni = 0; ni < 4; ni++) {
            const int col = bn + wn + ni * 8 + 2 * t;
            const float bx = __ldg(bias + col);
            const float by = __ldg(bias + col + 1);
            const int rr0 = bm + wm + mi * 16 + g;
            float2 v0, v1;
            v0.x = acc[mi][ni][0] + bx; v0.y = acc[mi][ni][1] + by;
            v1.x = acc[mi][ni][2] + bx; v1.y = acc[mi][ni][3] + by;
            *(float2*)(C + (size_t)rr0 * HIDDEN + col) = v0;
            *(float2*)(C + (size_t)(rr0 + 8) * HIDDEN + col) = v1;
        }
}

// ---------------------------------------------------------------------------
// fp16 flash attention, register-resident P (FA-2 style).
// CTA = (128-query tile, head, batch). 256 threads = 8 warps x 16 q-rows.
// Q fragments hoisted to registers; S C-fragments ARE the PV A-fragments
// (m16n8k16 row.col layout identity) so P never touches SMEM.
// K/Vt tiles double-buffered via cp.async.
// SMEM (uint32): Qs 128x36 | Ks 2x64x36 | Vt 2x64x36 = 55296 B -> 2 CTAs/SM.
// ---------------------------------------------------------------------------
#define ASM_BYTES ((128 * 36 + 2 * 64 * 36 + 2 * 64 * 36) * 4)

__global__ __launch_bounds__(256, 2) void attn_mma(
    const uint32_t* __restrict__ Qh, const uint32_t* __restrict__ Kh,
    const uint32_t* __restrict__ Vth, uint32_t* __restrict__ Oh)
{
    extern __shared__ uint32_t sm32[];
    uint32_t* Qs = sm32;                     // [128][36] (staging only)
    uint32_t* KsB = Qs + 128 * 36;           // [2][64][36] (key x d-pair)
    uint32_t* VtB = KsB + 2 * 64 * 36;       // [2][64][36] (d x key-pair)
    const uint32_t sbase = smem_u32(sm32);
    const uint32_t ks_off = (uint32_t)(128 * 36) * 4u;
    const uint32_t vt_off = ks_off + 2u * 64u * 36u * 4u;

    const int tid = threadIdx.x;
    const int wid = tid >> 5;
    const int lane = tid & 31;
    const int g = lane >> 2;
    const int t = lane & 3;
    const int qb = blockIdx.x;
    const int h  = blockIdx.y;
    const int b  = blockIdx.z;
    const int kvh = h >> 2;

    const uint32_t* Kbase  = Kh + (size_t)(b * SEQ) * (KVDIM / 2) + kvh * (HDIM / 2);
    const uint32_t* Vtbase = Vth + (size_t)((b * NKV + kvh) * HDIM) * (SEQ / 2);

    // cp.async one K/Vt tile pair into buffer s (2 x uint4 per thread each)
    auto issue = [&](int jb, int s) {
#pragma unroll
        for (int j = 0; j < 2; j++) {
            int idx = j * 256 + tid;
            int r = idx >> 3, c4 = (idx & 7) * 4;
            uint32_t so = (uint32_t)(s * 64 * 36 + r * 36 + c4) * 4u;
            cpasync16(sbase + ks_off + so, Kbase + (size_t)(jb * 64 + r) * (KVDIM / 2) + c4);
            cpasync16(sbase + vt_off + so, Vtbase + (size_t)r * (SEQ / 2) + jb * 32 + c4);
        }
        asm volatile("cp.async.commit_group;" ::: "memory");
    };

    issue(0, 0);   // prefetch first tile immediately

    // Stage Q tile (coalesced), scale by 1/8
    {
        const __half2 sc = __float2half2_rn(0.125f);
        const uint32_t* src = Qh + (size_t)(b * SEQ + qb * 128) * (HIDDEN / 2) + h * (HDIM / 2);
#pragma unroll
        for (int j = 0; j < 4; j++) {
            int idx = j * 256 + tid;
            int r = idx >> 3, c = (idx & 7) * 4;
            uint4 v = *(const uint4*)(src + (size_t)r * (HIDDEN / 2) + c);
            __half2* hp = (__half2*)&v;
            hp[0] = __hmul2(hp[0], sc); hp[1] = __hmul2(hp[1], sc);
            hp[2] = __hmul2(hp[2], sc); hp[3] = __hmul2(hp[3], sc);
            uint32_t* dst = &Qs[r * 36 + c];
            dst[0] = v.x; dst[1] = v.y; dst[2] = v.z; dst[3] = v.w;
        }
    }
    __syncthreads();

    // Hoist Q fragments to registers (loop-invariant)
    const int qr = wid * 16 + g;
    uint32_t qf[4][4];
#pragma unroll
    for (int kk = 0; kk < 4; kk++) {
        const int kc = kk * 8 + t;
        qf[kk][0] = Qs[qr * 36 + kc];
        qf[kk][1] = Qs[(qr + 8) * 36 + kc];
        qf[kk][2] = Qs[qr * 36 + kc + 4];
        qf[kk][3] = Qs[(qr + 8) * 36 + kc + 4];
    }

    float acc_o[8][4] = {};
    float m0 = -1e30f, m1 = -1e30f, l0 = 0.f, l1 = 0.f;

    for (int jb = 0; jb < SEQ / 64; jb++) {
        const int s = jb & 1;
        if (jb + 1 < SEQ / 64) {
            issue(jb + 1, s ^ 1);
            asm volatile("cp.async.wait_group %0;" :: "n"(1) : "memory");
        } else {
            asm volatile("cp.async.wait_group %0;" :: "n"(0) : "memory");
        }
        __syncthreads();

        const uint32_t* Ks = KsB + s * 64 * 36;
        const uint32_t* Vt = VtB + s * 64 * 36;

        // S = Q K^T : 4 k16 steps over D=64
        float acc_s[8][4] = {};
#pragma unroll
        for (int kk = 0; kk < 4; kk++) {
            const int kc = kk * 8 + t;
#pragma unroll
            for (int ni = 0; ni < 8; ni++) {
                uint32_t bf[2];
                bf[0] = Ks[(ni * 8 + g) * 36 + kc];
                bf[1] = Ks[(ni * 8 + g) * 36 + kc + 4];
                mma_f16(acc_s[ni], qf[kk], bf);
            }
        }

        // Fragment online softmax (rows qr, qr+8; 16 cols/thread)
        float mx0 = -1e30f, mx1 = -1e30f;
#pragma unroll
        for (int ni = 0; ni < 8; ni++) {
            mx0 = fmaxf(mx0, fmaxf(acc_s[ni][0], acc_s[ni][1]));
            mx1 = fmaxf(mx1, fmaxf(acc_s[ni][2], acc_s[ni][3]));
        }
        mx0 = fmaxf(mx0, __shfl_xor_sync(0xffffffffu, mx0, 1));
        mx0 = fmaxf(mx0, __shfl_xor_sync(0xffffffffu, mx0, 2));
        mx1 = fmaxf(mx1, __shfl_xor_sync(0xffffffffu, mx1, 1));
        mx1 = fmaxf(mx1, __shfl_xor_sync(0xffffffffu, mx1, 2));
        const float mn0 = fmaxf(m0, mx0);
        const float mn1 = fmaxf(m1, mx1);
        const float sf0 = __expf(m0 - mn0);
        const float sf1 = __expf(m1 - mn1);
        m0 = mn0; m1 = mn1;

#pragma unroll
        for (int dn = 0; dn < 8; dn++) {
            acc_o[dn][0] *= sf0; acc_o[dn][1] *= sf0;
            acc_o[dn][2] *= sf1; acc_o[dn][3] *= sf1;
        }

        // P = exp(S - m): pack DIRECTLY into PV A-fragments (layout identity)
        uint32_t pf[4][4];
        float rs0 = 0.f, rs1 = 0.f;
#pragma unroll
        for (int kb = 0; kb < 4; kb++) {
#pragma unroll
            for (int half = 0; half < 2; half++) {
                const int ni = 2 * kb + half;
                float p0 = __expf(acc_s[ni][0] - mn0);
                float p1 = __expf(acc_s[ni][1] - mn0);
                float p2 = __expf(acc_s[ni][2] - mn1);
                float p3 = __expf(acc_s[ni][3] - mn1);
                rs0 += p0 + p1;
                rs1 += p2 + p3;
                __half2 w0 = __floats2half2_rn(p0, p1);
                __half2 w1 = __floats2half2_rn(p2, p3);
                pf[kb][half * 2 + 0] = *(uint32_t*)&w0;   // rows g / g+8
                pf[kb][half * 2 + 1] = *(uint32_t*)&w1;
            }
        }
        rs0 += __shfl_xor_sync(0xffffffffu, rs0, 1);
        rs0 += __shfl_xor_sync(0xffffffffu, rs0, 2);
        rs1 += __shfl_xor_sync(0xffffffffu, rs1, 1);
        rs1 += __shfl_xor_sync(0xffffffffu, rs1, 2);
        l0 = l0 * sf0 + rs0;
        l1 = l1 * sf1 + rs1;

        // O += P V : 4 k16 steps over 64 keys, P from registers
#pragma unroll
        for (int kb = 0; kb < 4; kb++) {
            const int kc = kb * 8 + t;
#pragma unroll
            for (int dn = 0; dn < 8; dn++) {
                uint32_t bf[2];
                bf[0] = Vt[(dn * 8 + g) * 36 + kc];
                bf[1] = Vt[(dn * 8 + g) * 36 + kc + 4];
                mma_f16(acc_o[dn], pf[kb], bf);
            }
        }
        __syncthreads();   // all warps done with buffer s before it is refilled
    }

    // Epilogue: normalize, store fp16 (feeds O-proj mma)
    const float i0 = 1.f / l0;
    const float i1 = 1.f / l1;
    const int row0 = b * SEQ + qb * 128 + qr;
#pragma unroll
    for (int dn = 0; dn < 8; dn++) {
        const int cp = h * (HDIM / 2) + dn * 4 + t;
        __half2 h0 = __floats2half2_rn(acc_o[dn][0] * i0, acc_o[dn][1] * i0);
        __half2 h1 = __floats2half2_rn(acc_o[dn][2] * i1, acc_o[dn][3] * i1);
        Oh[(size_t)row0 * (HIDDEN / 2) + cp] = *(uint32_t*)&h0;
        Oh[(size_t)(row0 + 8) * (HIDDEN / 2) + cp] = *(uint32_t*)&h1;
    }
}

// ---------------------------------------------------------------------------
extern "C" void kernel_launch(void* const* d_in, const int* in_sizes, int n_in,
                              void* d_out, int out_size)
{
    const float* x  = (const float*)d_in[0];
    const float* wq = (const float*)d_in[1];
    const float* bq = (const float*)d_in[2];
    const float* wk = (const float*)d_in[3];
    const float* bk = (const float*)d_in[4];
    const float* wv = (const float*)d_in[5];
    const float* bv = (const float*)d_in[6];
    const float* wo = (const float*)d_in[7];
    const float* bo = (const float*)d_in[8];
    float* out = (float*)d_out;

    __half *xh, *wqkvh, *woh, *qh, *kh, *vt, *oh;
    cudaGetSymbolAddress((void**)&xh, g_xh);
    cudaGetSymbolAddress((void**)&wqkvh, g_wqkvh);
    cudaGetSymbolAddress((void**)&woh, g_woh);
    cudaGetSymbolAddress((void**)&qh, g_qh);
    cudaGetSymbolAddress((void**)&kh, g_kh);
    cudaGetSymbolAddress((void**)&vt, g_vt);
    cudaGetSymbolAddress((void**)&oh, g_oh);

    cudaFuncSetAttribute(gemm_qkv,   cudaFuncAttributeMaxDynamicSharedMemorySize, GSM_BYTES);
    cudaFuncSetAttribute(gemm_oproj, cudaFuncAttributeMaxDynamicSharedMemorySize, GSM_BYTES);
    cudaFuncSetAttribute(attn_mma,   cudaFuncAttributeMaxDynamicSharedMemorySize, ASM_BYTES);

    cvt_f16<<<(MROWS * HIDDEN / 4 + 255) / 256, 256>>>((const float4*)x,  (uint2*)xh, MROWS * HIDDEN / 4);
    cvt_f16<<<(HIDDEN * HIDDEN / 4 + 255) / 256, 256>>>((const float4*)wq, (uint2*)wqkvh, HIDDEN * HIDDEN / 4);
    cvt_f16<<<(KVDIM * HIDDEN / 4 + 255) / 256, 256>>>((const float4*)wk, (uint2*)(wqkvh + (size_t)HIDDEN * HIDDEN), KVDIM * HIDDEN / 4);
    cvt_f16<<<(KVDIM * HIDDEN / 4 + 255) / 256, 256>>>((const float4*)wv, (uint2*)(wqkvh + (size_t)(HIDDEN + KVDIM) * HIDDEN), KVDIM * HIDDEN / 4);
    cvt_f16<<<(HIDDEN * HIDDEN / 4 + 255) / 256, 256>>>((const float4*)wo, (uint2*)woh, HIDDEN * HIDDEN / 4);

    gemm_qkv<<<dim3(NQKV / 128, MROWS / 128), 256, GSM_BYTES>>>(
        (const uint32_t*)xh, (const uint32_t*)wqkvh, bq, bk, bv,
        (uint32_t*)qh, (uint32_t*)kh, vt);

    attn_mma<<<dim3(SEQ / 128, NHEADS, BATCH), 256, ASM_BYTES>>>(
        (const uint32_t*)qh, (const uint32_t*)kh, (const uint32_t*)vt, (uint32_t*)oh);

    gemm_oproj<<<dim3(HIDDEN / 128, MROWS / 128), 256, GSM_BYTES>>>(
        (const uint32_t*)oh, (const uint32_t*)woh, bo, out);
}

// round 11
// speedup vs baseline: 8.5767x; 1.1338x over previous
#include <cuda_runtime.h>
#include <cuda_fp16.h>
#include <cstdint>

// Problem constants
#define BATCH 2
#define SEQ 2048
#define HIDDEN 2048
#define NHEADS 32
#define NKV 8
#define HDIM 64
#define KVDIM 512
#define MROWS (BATCH * SEQ)        // 4096
#define NQKV (HIDDEN + 2 * KVDIM)  // 3072

// Scratch (allocation-free rule: __device__ globals), all fp16
__device__ __align__(16) __half g_xh[MROWS * HIDDEN];
__device__ __align__(16) __half g_wqkvh[NQKV * HIDDEN];
__device__ __align__(16) __half g_woh[HIDDEN * HIDDEN];
__device__ __align__(16) __half g_qh[MROWS * HIDDEN];
__device__ __align__(16) __half g_kh[MROWS * KVDIM];
__device__ __align__(16) __half g_vt[BATCH * NKV * HDIM * SEQ];  // [b,kvh,d][s]
__device__ __align__(16) __half g_oh[MROWS * HIDDEN];

__device__ __forceinline__ void mma_f16(float* d, const uint32_t* a, const uint32_t* b) {
    asm volatile(
        "mma.sync.aligned.m16n8k16.row.col.f32.f16.f16.f32 "
        "{%0,%1,%2,%3}, {%4,%5,%6,%7}, {%8,%9}, {%0,%1,%2,%3};"
        : "+f"(d[0]), "+f"(d[1]), "+f"(d[2]), "+f"(d[3])
        : "r"(a[0]), "r"(a[1]), "r"(a[2]), "r"(a[3]), "r"(b[0]), "r"(b[1]));
}

#define LDSM4(r0, r1, r2, r3, addr) \
    asm volatile("ldmatrix.sync.aligned.m8n8.x4.shared.b16 {%0,%1,%2,%3}, [%4];" \
        : "=r"(r0), "=r"(r1), "=r"(r2), "=r"(r3) : "r"(addr))

__device__ __forceinline__ uint32_t smem_u32(const void* p) {
    uint32_t a;
    asm("{ .reg .u64 t; cvta.to.shared.u64 t, %1; cvt.u32.u64 %0, t; }" : "=r"(a) : "l"(p));
    return a;
}

__device__ __forceinline__ void cpasync16(uint32_t dst, const void* src) {
    asm volatile("cp.async.ca.shared.global [%0], [%1], 16;" :: "r"(dst), "l"(src));
}

// ---------------------------------------------------------------------------
// Fused fp32 -> fp16 conversion for all five tensors (single launch)
// ---------------------------------------------------------------------------
#define X4C (MROWS * HIDDEN / 4)
#define Q4C (HIDDEN * HIDDEN / 4)
#define K4C (KVDIM * HIDDEN / 4)
#define TOT4 (X4C + Q4C + 2 * K4C + Q4C)

__global__ void cvt_all(
    const float4* __restrict__ x,  const float4* __restrict__ wq,
    const float4* __restrict__ wk, const float4* __restrict__ wv,
    const float4* __restrict__ wo,
    uint2* __restrict__ xh, uint2* __restrict__ wqkvh, uint2* __restrict__ woh)
{
    int i = blockIdx.x * blockDim.x + threadIdx.x;
    if (i >= TOT4) return;
    float4 v;
    uint2* out;
    if (i < X4C)                      { v = x[i];                      out = xh + i; }
    else if (i < X4C + Q4C)           { int j = i - X4C;               v = wq[j]; out = wqkvh + j; }
    else if (i < X4C + Q4C + K4C)     { int j = i - X4C - Q4C;         v = wk[j]; out = wqkvh + Q4C + j; }
    else if (i < X4C + Q4C + 2 * K4C) { int j = i - X4C - Q4C - K4C;   v = wv[j]; out = wqkvh + Q4C + K4C + j; }
    else                              { int j = i - X4C - Q4C - 2*K4C; v = wo[j]; out = woh + j; }
    __half2 h0 = __floats2half2_rn(v.x, v.y);
    __half2 h1 = __floats2half2_rn(v.z, v.w);
    uint2 o;
    o.x = *(uint32_t*)&h0;
    o.y = *(uint32_t*)&h1;
    *out = o;
}

// ---------------------------------------------------------------------------
// fp16 GEMM core: C[M,N] = A[M,K] @ W[N,K]^T, fp32 accum, ldmatrix fragments.
// CTA 128x128, BK=32 (16 uint32/row), 256 threads (8 warps 2x4), warp 64x32.
// ---------------------------------------------------------------------------
#define TS 20
#define GSM_BYTES (3 * 2 * 128 * TS * 4)

struct GemmCore {
    uint32_t sbase;
    const uint32_t* A;
    const uint32_t* W;
    int K2;
    int bm, bn, tid;

    __device__ __forceinline__ void issue(int kt, int s) {
        const int k0u = kt << 4;
        const uint32_t so = (uint32_t)s * 5120u;
#pragma unroll
        for (int j = 0; j < 2; j++) {
            int idx = j * 256 + tid;
            int r = idx >> 2, c4 = idx & 3;
            uint32_t off = (so + (uint32_t)(r * TS + c4 * 4)) * 4u;
            cpasync16(sbase + off, A + (size_t)(bm + r) * K2 + k0u + c4 * 4);
            cpasync16(sbase + off + 2560u * 4u, W + (size_t)(bn + r) * K2 + k0u + c4 * 4);
        }
        asm volatile("cp.async.commit_group;" ::: "memory");
    }

    __device__ __forceinline__ void run(float acc[4][4][4], int wm, int wn, int lane) {
        // ldmatrix per-lane base addresses (within stage 0)
        const uint32_t a_base = sbase +
            (uint32_t)(((wm + (lane & 7) + ((lane >> 3) & 1) * 8) * TS + ((lane >> 4) & 1) * 4) * 4);
        const uint32_t b_base = sbase + 2560u * 4u +
            (uint32_t)(((wn + (lane & 7) + ((lane >> 4) & 1) * 8) * TS + ((lane >> 3) & 1) * 4) * 4);

        const int NT = K2 >> 4;
        issue(0, 0);
        issue(1, 1);
        for (int kt = 0; kt < NT; kt++) {
            asm volatile("cp.async.wait_group %0;" :: "n"(1) : "memory");
            __syncthreads();
            if (kt + 2 < NT) issue(kt + 2, (kt + 2) % 3);
            const uint32_t so = (uint32_t)(kt % 3) * 5120u * 4u;
#pragma unroll
            for (int kk = 0; kk < 2; kk++) {
                const uint32_t ko = (uint32_t)(kk * 8) * 4u;
                uint32_t af[4][4];
#pragma unroll
                for (int mi = 0; mi < 4; mi++)
                    LDSM4(af[mi][0], af[mi][1], af[mi][2], af[mi][3],
                          a_base + so + ko + (uint32_t)(mi * 16 * TS) * 4u);
                uint32_t bf[4][2];
#pragma unroll
                for (int p = 0; p < 2; p++)
                    LDSM4(bf[2*p][0], bf[2*p][1], bf[2*p+1][0], bf[2*p+1][1],
                          b_base + so + ko + (uint32_t)(p * 16 * TS) * 4u);
#pragma unroll
                for (int mi = 0; mi < 4; mi++)
#pragma unroll
                    for (int ni = 0; ni < 4; ni++)
                        mma_f16(acc[mi][ni], af[mi], bf[ni]);
            }
        }
    }
};

// Fused QKV projection; q/k written fp16 row-major, v written fp16 TRANSPOSED.
__global__ __launch_bounds__(256, 2) void gemm_qkv(
    const uint32_t* __restrict__ A, const uint32_t* __restrict__ Wc,
    const float* __restrict__ bq, const float* __restrict__ bk, const float* __restrict__ bv,
    uint32_t* __restrict__ q, uint32_t* __restrict__ k, __half* __restrict__ vt)
{
    extern __shared__ uint32_t sh[];
    const int tid = threadIdx.x;
    const int wid = tid >> 5;
    const int lane = tid & 31;
    const int g = lane >> 2, t = lane & 3;
    const int wm = (wid & 1) * 64, wn = (wid >> 1) * 32;
    const int bm = blockIdx.y * 128, bn = blockIdx.x * 128;

    GemmCore core{smem_u32(sh), A, Wc, HIDDEN / 2, bm, bn, tid};
    float acc[4][4][4] = {};
    core.run(acc, wm, wn, lane);

    if (bn < HIDDEN) {
        const float* bias = bq;
#pragma unroll
        for (int mi = 0; mi < 4; mi++)
#pragma unroll
            for (int ni = 0; ni < 4; ni++) {
                const int col = bn + wn + ni * 8 + 2 * t;
                const float bx = __ldg(bias + col);
                const float by = __ldg(bias + col + 1);
                const int rr0 = bm + wm + mi * 16 + g;
                __half2 h0 = __floats2half2_rn(acc[mi][ni][0] + bx, acc[mi][ni][1] + by);
                __half2 h1 = __floats2half2_rn(acc[mi][ni][2] + bx, acc[mi][ni][3] + by);
                q[(size_t)rr0 * (HIDDEN / 2) + (col >> 1)] = *(uint32_t*)&h0;
                q[(size_t)(rr0 + 8) * (HIDDEN / 2) + (col >> 1)] = *(uint32_t*)&h1;
            }
    } else if (bn < HIDDEN + KVDIM) {
        const float* bias = bk;
        const int cb = bn - HIDDEN;
#pragma unroll
        for (int mi = 0; mi < 4; mi++)
#pragma unroll
            for (int ni = 0; ni < 4; ni++) {
                const int col = cb + wn + ni * 8 + 2 * t;
                const float bx = __ldg(bias + col);
                const float by = __ldg(bias + col + 1);
                const int rr0 = bm + wm + mi * 16 + g;
                __half2 h0 = __floats2half2_rn(acc[mi][ni][0] + bx, acc[mi][ni][1] + by);
                __half2 h1 = __floats2half2_rn(acc[mi][ni][2] + bx, acc[mi][ni][3] + by);
                k[(size_t)rr0 * (KVDIM / 2) + (col >> 1)] = *(uint32_t*)&h0;
                k[(size_t)(rr0 + 8) * (KVDIM / 2) + (col >> 1)] = *(uint32_t*)&h1;
            }
    } else {
        const float* bias = bv;
        const int cb = bn - HIDDEN - KVDIM;
#pragma unroll
        for (int mi = 0; mi < 4; mi++)
#pragma unroll
            for (int ni = 0; ni < 4; ni++) {
                const int col = cb + wn + ni * 8 + 2 * t;   // d index (even)
                const float bx = __ldg(bias + col);
                const float by = __ldg(bias + col + 1);
#pragma unroll
                for (int rr = 0; rr < 2; rr++) {
                    const int row = bm + wm + mi * 16 + g + rr * 8;
                    const int bb = row >> 11;
                    const int s  = row & 2047;
                    const float v0 = acc[mi][ni][rr * 2 + 0] + bx;
                    const float v1 = acc[mi][ni][rr * 2 + 1] + by;
                    const size_t base = ((size_t)(bb * NKV + (col >> 6)) * HDIM);
                    vt[(base + (col & 63)) * SEQ + s]     = __float2half_rn(v0);
                    vt[(base + (col & 63) + 1) * SEQ + s] = __float2half_rn(v1);
                }
            }
    }
}

// O-projection: fp16 inputs, fp32 output + bias.
__global__ __launch_bounds__(256, 2) void gemm_oproj(
    const uint32_t* __restrict__ A, const uint32_t* __restrict__ W,
    const float* __restrict__ bias, float* __restrict__ C)
{
    extern __shared__ uint32_t sh[];
    const int tid = threadIdx.x;
    const int wid = tid >> 5;
    const int lane = tid & 31;
    const int g = lane >> 2, t = lane & 3;
    const int wm = (wid & 1) * 64, wn = (wid >> 1) * 32;
    const int bm = blockIdx.y * 128, bn = blockIdx.x * 128;

    GemmCore core{smem_u32(sh), A, W, HIDDEN / 2, bm, bn, tid};
    float acc[4][4][4] = {};
    core.run(acc, wm, wn, lane);

#pragma unroll
    for (int mi = 0; mi < 4; mi++)
#pragma unroll
        for (int ni = 0; ni < 4; ni++) {
            const int col = bn + wn + ni * 8 + 2 * t;
            const float bx = __ldg(bias + col);
            const float by = __ldg(bias + col + 1);
            const int rr0 = bm + wm + mi * 16 + g;
            float2 v0, v1;
            v0.x = acc[mi][ni][0] + bx; v0.y = acc[mi][ni][1] + by;
            v1.x = acc[mi][ni][2] + bx; v1.y = acc[mi][ni][3] + by;
            *(float2*)(C + (size_t)rr0 * HIDDEN + col) = v0;
            *(float2*)(C + (size_t)(rr0 + 8) * HIDDEN + col) = v1;
        }
}

// ---------------------------------------------------------------------------
// fp16 flash attention: register-resident P, ldmatrix K/V fragments,
// double-buffered cp.async K/Vt tiles.
// SMEM (uint32): Qs 128x36 | Ks 2x64x36 | Vt 2x64x36 = 55296 B -> 2 CTAs/SM.
// ---------------------------------------------------------------------------
#define ASM_BYTES ((128 * 36 + 2 * 64 * 36 + 2 * 64 * 36) * 4)

__global__ __launch_bounds__(256, 2) void attn_mma(
    const uint32_t* __restrict__ Qh, const uint32_t* __restrict__ Kh,
    const uint32_t* __restrict__ Vth, uint32_t* __restrict__ Oh)
{
    extern __shared__ uint32_t sm32[];
    uint32_t* Qs = sm32;                     // [128][36] (staging only)
    const uint32_t sbase = smem_u32(sm32);
    const uint32_t ks_off = (uint32_t)(128 * 36) * 4u;
    const uint32_t vt_off = ks_off + 2u * 64u * 36u * 4u;

    const int tid = threadIdx.x;
    const int wid = tid >> 5;
    const int lane = tid & 31;
    const int g = lane >> 2;
    const int t = lane & 3;
    const int qb = blockIdx.x;
    const int h  = blockIdx.y;
    const int b  = blockIdx.z;
    const int kvh = h >> 2;

    const uint32_t* Kbase  = Kh + (size_t)(b * SEQ) * (KVDIM / 2) + kvh * (HDIM / 2);
    const uint32_t* Vtbase = Vth + (size_t)((b * NKV + kvh) * HDIM) * (SEQ / 2);

    // ldmatrix per-lane base offsets (B-operand pattern) within a tile
    const uint32_t bl_off =
        (uint32_t)((((lane & 7) + ((lane >> 4) & 1) * 8) * 36 + ((lane >> 3) & 1) * 4) * 4);

    auto issue = [&](int jb, int s) {
#pragma unroll
        for (int j = 0; j < 2; j++) {
            int idx = j * 256 + tid;
            int r = idx >> 3, c4 = (idx & 7) * 4;
            uint32_t so = (uint32_t)(s * 64 * 36 + r * 36 + c4) * 4u;
            cpasync16(sbase + ks_off + so, Kbase + (size_t)(jb * 64 + r) * (KVDIM / 2) + c4);
            cpasync16(sbase + vt_off + so, Vtbase + (size_t)r * (SEQ / 2) + jb * 32 + c4);
        }
        asm volatile("cp.async.commit_group;" ::: "memory");
    };

    issue(0, 0);

    // Stage Q tile (coalesced), scale by 1/8
    {
        const __half2 sc = __float2half2_rn(0.125f);
        const uint32_t* src = Qh + (size_t)(b * SEQ + qb * 128) * (HIDDEN / 2) + h * (HDIM / 2);
#pragma unroll
        for (int j = 0; j < 4; j++) {
            int idx = j * 256 + tid;
            int r = idx >> 3, c = (idx & 7) * 4;
            uint4 v = *(const uint4*)(src + (size_t)r * (HIDDEN / 2) + c);
            __half2* hp = (__half2*)&v;
            hp[0] = __hmul2(hp[0], sc); hp[1] = __hmul2(hp[1], sc);
            hp[2] = __hmul2(hp[2], sc); hp[3] = __hmul2(hp[3], sc);
            uint32_t* dst = &Qs[r * 36 + c];
            dst[0] = v.x; dst[1] = v.y; dst[2] = v.z; dst[3] = v.w;
        }
    }
    __syncthreads();

    // Hoist Q fragments to registers (loop-invariant)
    const int qr = wid * 16 + g;
    uint32_t qf[4][4];
#pragma unroll
    for (int kk = 0; kk < 4; kk++) {
        const int kc = kk * 8 + t;
        qf[kk][0] = Qs[qr * 36 + kc];
        qf[kk][1] = Qs[(qr + 8) * 36 + kc];
        qf[kk][2] = Qs[qr * 36 + kc + 4];
        qf[kk][3] = Qs[(qr + 8) * 36 + kc + 4];
    }

    float acc_o[8][4] = {};
    float m0 = -1e30f, m1 = -1e30f, l0 = 0.f, l1 = 0.f;

    for (int jb = 0; jb < SEQ / 64; jb++) {
        const int s = jb & 1;
        if (jb + 1 < SEQ / 64) {
            issue(jb + 1, s ^ 1);
            asm volatile("cp.async.wait_group %0;" :: "n"(1) : "memory");
        } else {
            asm volatile("cp.async.wait_group %0;" :: "n"(0) : "memory");
        }
        __syncthreads();

        const uint32_t kf_base = sbase + ks_off + (uint32_t)(s * 64 * 36) * 4u + bl_off;
        const uint32_t vf_base = sbase + vt_off + (uint32_t)(s * 64 * 36) * 4u + bl_off;

        // S = Q K^T : 4 k16 steps over D=64, K frags via ldmatrix
        float acc_s[8][4] = {};
#pragma unroll
        for (int kk = 0; kk < 4; kk++) {
            const uint32_t ko = (uint32_t)(kk * 8) * 4u;
#pragma unroll
            for (int p = 0; p < 4; p++) {
                uint32_t bf[4];
                LDSM4(bf[0], bf[1], bf[2], bf[3], kf_base + ko + (uint32_t)(p * 16 * 36) * 4u);
                mma_f16(acc_s[2*p],     qf[kk], bf);
                mma_f16(acc_s[2*p + 1], qf[kk], bf + 2);
            }
        }

        // Fragment online softmax (rows qr, qr+8; 16 cols/thread)
        float mx0 = -1e30f, mx1 = -1e30f;
#pragma unroll
        for (int ni = 0; ni < 8; ni++) {
            mx0 = fmaxf(mx0, fmaxf(acc_s[ni][0], acc_s[ni][1]));
            mx1 = fmaxf(mx1, fmaxf(acc_s[ni][2], acc_s[ni][3]));
        }
        mx0 = fmaxf(mx0, __shfl_xor_sync(0xffffffffu, mx0, 1));
        mx0 = fmaxf(mx0, __shfl_xor_sync(0xffffffffu, mx0, 2));
        mx1 = fmaxf(mx1, __shfl_xor_sync(0xffffffffu, mx1, 1));
        mx1 = fmaxf(mx1, __shfl_xor_sync(0xffffffffu, mx1, 2));
        const float mn0 = fmaxf(m0, mx0);
        const float mn1 = fmaxf(m1, mx1);
        const float sf0 = __expf(m0 - mn0);
        const float sf1 = __expf(m1 - mn1);
        m0 = mn0; m1 = mn1;

#pragma unroll
        for (int dn = 0; dn < 8; dn++) {
            acc_o[dn][0] *= sf0; acc_o[dn][1] *= sf0;
            acc_o[dn][2] *= sf1; acc_o[dn][3] *= sf1;
        }

        // P = exp(S - m): pack directly into PV A-fragments (layout identity)
        uint32_t pf[4][4];
        float rs0 = 0.f, rs1 = 0.f;
#pragma unroll
        for (int kb = 0; kb < 4; kb++) {
#pragma unroll
            for (int half = 0; half < 2; half++) {
                const int ni = 2 * kb + half;
                float p0 = __expf(acc_s[ni][0] - mn0);
                float p1 = __expf(acc_s[ni][1] - mn0);
                float p2 = __expf(acc_s[ni][2] - mn1);
                float p3 = __expf(acc_s[ni][3] - mn1);
                rs0 += p0 + p1;
                rs1 += p2 + p3;
                __half2 w0 = __floats2half2_rn(p0, p1);
                __half2 w1 = __floats2half2_rn(p2, p3);
                pf[kb][half * 2 + 0] = *(uint32_t*)&w0;
                pf[kb][half * 2 + 1] = *(uint32_t*)&w1;
            }
        }
        rs0 += __shfl_xor_sync(0xffffffffu, rs0, 1);
        rs0 += __shfl_xor_sync(0xffffffffu, rs0, 2);
        rs1 += __shfl_xor_sync(0xffffffffu, rs1, 1);
        rs1 += __shfl_xor_sync(0xffffffffu, rs1, 2);
        l0 = l0 * sf0 + rs0;
        l1 = l1 * sf1 + rs1;

        // O += P V : V frags via ldmatrix, P from registers
#pragma unroll
        for (int kb = 0; kb < 4; kb++) {
            const uint32_t ko = (uint32_t)(kb * 8) * 4u;
#pragma unroll
            for (int p = 0; p < 4; p++) {
                uint32_t bf[4];
                LDSM4(bf[0], bf[1], bf[2], bf[3], vf_base + ko + (uint32_t)(p * 16 * 36) * 4u);
                mma_f16(acc_o[2*p],     pf[kb], bf);
                mma_f16(acc_o[2*p + 1], pf[kb], bf + 2);
            }
        }
        __syncthreads();   // all warps done with buffer s before refill
    }

    // Epilogue: normalize, store fp16 (feeds O-proj mma)
    const float i0 = 1.f / l0;
    const float i1 = 1.f / l1;
    const int row0 = b * SEQ + qb * 128 + qr;
#pragma unroll
    for (int dn = 0; dn < 8; dn++) {
        const int cp = h * (HDIM / 2) + dn * 4 + t;
        __half2 h0 = __floats2half2_rn(acc_o[dn][0] * i0, acc_o[dn][1] * i0);
        __half2 h1 = __floats2half2_rn(acc_o[dn][2] * i1, acc_o[dn][3] * i1);
        Oh[(size_t)row0 * (HIDDEN / 2) + cp] = *(uint32_t*)&h0;
        Oh[(size_t)(row0 + 8) * (HIDDEN / 2) + cp] = *(uint32_t*)&h1;
    }
}

// ---------------------------------------------------------------------------
extern "C" void kernel_launch(void* const* d_in, const int* in_sizes, int n_in,
                              void* d_out, int out_size)
{
    const float* x  = (const float*)d_in[0];
    const float* wq = (const float*)d_in[1];
    const float* bq = (const float*)d_in[2];
    const float* wk = (const float*)d_in[3];
    const float* bk = (const float*)d_in[4];
    const float* wv = (const float*)d_in[5];
    const float* bv = (const float*)d_in[6];
    const float* wo = (const float*)d_in[7];
    const float* bo = (const float*)d_in[8];
    float* out = (float*)d_out;

    __half *xh, *wqkvh, *woh, *qh, *kh, *vt, *oh;
    cudaGetSymbolAddress((void**)&xh, g_xh);
    cudaGetSymbolAddress((void**)&wqkvh, g_wqkvh);
    cudaGetSymbolAddress((void**)&woh, g_woh);
    cudaGetSymbolAddress((void**)&qh, g_qh);
    cudaGetSymbolAddress((void**)&kh, g_kh);
    cudaGetSymbolAddress((void**)&vt, g_vt);
    cudaGetSymbolAddress((void**)&oh, g_oh);

    cudaFuncSetAttribute(gemm_qkv,   cudaFuncAttributeMaxDynamicSharedMemorySize, GSM_BYTES);
    cudaFuncSetAttribute(gemm_oproj, cudaFuncAttributeMaxDynamicSharedMemorySize, GSM_BYTES);
    cudaFuncSetAttribute(attn_mma,   cudaFuncAttributeMaxDynamicSharedMemorySize, ASM_BYTES);

    // Single fused conversion launch
    cvt_all<<<(TOT4 + 255) / 256, 256>>>(
        (const float4*)x, (const float4*)wq, (const float4*)wk,
        (const float4*)wv, (const float4*)wo,
        (uint2*)xh, (uint2*)wqkvh, (uint2*)woh);

    gemm_qkv<<<dim3(NQKV / 128, MROWS / 128), 256, GSM_BYTES>>>(
        (const uint32_t*)xh, (const uint32_t*)wqkvh, bq, bk, bv,
        (uint32_t*)qh, (uint32_t*)kh, vt);

    attn_mma<<<dim3(SEQ / 128, NHEADS, BATCH), 256, ASM_BYTES>>>(
        (const uint32_t*)qh, (const uint32_t*)kh, (const uint32_t*)vt, (uint32_t*)oh);

    gemm_oproj<<<dim3(HIDDEN / 128, MROWS / 128), 256, GSM_BYTES>>>(
        (const uint32_t*)oh, (const uint32_t*)woh, bo, out);
}

// round 12
// speedup vs baseline: 8.8451x; 1.0313x over previous
#include <cuda_runtime.h>
#include <cuda_fp16.h>
#include <cstdint>

// Problem constants
#define BATCH 2
#define SEQ 2048
#define HIDDEN 2048
#define NHEADS 32
#define NKV 8
#define HDIM 64
#define KVDIM 512
#define MROWS (BATCH * SEQ)        // 4096
#define NQKV (HIDDEN + 2 * KVDIM)  // 3072

// Scratch (allocation-free rule: __device__ globals), all fp16
__device__ __align__(16) __half g_xh[MROWS * HIDDEN];
__device__ __align__(16) __half g_wqkvh[NQKV * HIDDEN];
__device__ __align__(16) __half g_woh[HIDDEN * HIDDEN];
__device__ __align__(16) __half g_qh[MROWS * HIDDEN];
__device__ __align__(16) __half g_kh[MROWS * KVDIM];
__device__ __align__(16) __half g_vt[BATCH * NKV * HDIM * SEQ];  // [b,kvh,d][s]
__device__ __align__(16) __half g_oh[MROWS * HIDDEN];

__device__ __forceinline__ void mma_f16(float* d, const uint32_t* a, const uint32_t* b) {
    asm volatile(
        "mma.sync.aligned.m16n8k16.row.col.f32.f16.f16.f32 "
        "{%0,%1,%2,%3}, {%4,%5,%6,%7}, {%8,%9}, {%0,%1,%2,%3};"
        : "+f"(d[0]), "+f"(d[1]), "+f"(d[2]), "+f"(d[3])
        : "r"(a[0]), "r"(a[1]), "r"(a[2]), "r"(a[3]), "r"(b[0]), "r"(b[1]));
}

#define LDSM4(r0, r1, r2, r3, addr) \
    asm volatile("ldmatrix.sync.aligned.m8n8.x4.shared.b16 {%0,%1,%2,%3}, [%4];" \
        : "=r"(r0), "=r"(r1), "=r"(r2), "=r"(r3) : "r"(addr))

__device__ __forceinline__ uint32_t smem_u32(const void* p) {
    uint32_t a;
    asm("{ .reg .u64 t; cvta.to.shared.u64 t, %1; cvt.u32.u64 %0, t; }" : "=r"(a) : "l"(p));
    return a;
}

__device__ __forceinline__ void cpasync16(uint32_t dst, const void* src) {
    asm volatile("cp.async.ca.shared.global [%0], [%1], 16;" :: "r"(dst), "l"(src));
}

// ---------------------------------------------------------------------------
// Fused fp32 -> fp16 conversion for all five tensors (single launch)
// ---------------------------------------------------------------------------
#define X4C (MROWS * HIDDEN / 4)
#define Q4C (HIDDEN * HIDDEN / 4)
#define K4C (KVDIM * HIDDEN / 4)
#define TOT4 (X4C + Q4C + 2 * K4C + Q4C)

__global__ void cvt_all(
    const float4* __restrict__ x,  const float4* __restrict__ wq,
    const float4* __restrict__ wk, const float4* __restrict__ wv,
    const float4* __restrict__ wo,
    uint2* __restrict__ xh, uint2* __restrict__ wqkvh, uint2* __restrict__ woh)
{
    int i = blockIdx.x * blockDim.x + threadIdx.x;
    if (i >= TOT4) return;
    float4 v;
    uint2* out;
    if (i < X4C)                      { v = x[i];                      out = xh + i; }
    else if (i < X4C + Q4C)           { int j = i - X4C;               v = wq[j]; out = wqkvh + j; }
    else if (i < X4C + Q4C + K4C)     { int j = i - X4C - Q4C;         v = wk[j]; out = wqkvh + Q4C + j; }
    else if (i < X4C + Q4C + 2 * K4C) { int j = i - X4C - Q4C - K4C;   v = wv[j]; out = wqkvh + Q4C + K4C + j; }
    else                              { int j = i - X4C - Q4C - 2*K4C; v = wo[j]; out = woh + j; }
    __half2 h0 = __floats2half2_rn(v.x, v.y);
    __half2 h1 = __floats2half2_rn(v.z, v.w);
    uint2 o;
    o.x = *(uint32_t*)&h0;
    o.y = *(uint32_t*)&h1;
    *out = o;
}

// ---------------------------------------------------------------------------
// fp16 GEMM core: C[M,N] = A[M,K] @ W[N,K]^T, fp32 accum, ldmatrix fragments.
// CTA 128x128, BK=64 (32 uint32/row, stride 36), 256 threads (8 warps 2x4),
// warp tile 64x32, 3-stage cp.async pipeline. SMEM 110592 B -> 2 CTAs/SM.
// ---------------------------------------------------------------------------
#define GTS 36
#define GSTAGE_W (128 * GTS)                 // words per operand per stage
#define GB_OFF_W (3 * GSTAGE_W)              // B region offset (words)
#define GSM_BYTES (2 * 3 * GSTAGE_W * 4)     // 110592

struct GemmCore {
    uint32_t sbase;
    const uint32_t* A;
    const uint32_t* W;
    int K2;
    int bm, bn, tid;

    __device__ __forceinline__ void issue(int kt, int s) {
        const int k0u = kt << 5;             // 32 uint32 per BK=64 tile
        const uint32_t so = (uint32_t)(s * GSTAGE_W);
#pragma unroll
        for (int j = 0; j < 4; j++) {
            int idx = j * 256 + tid;
            int r = idx >> 3, c4 = (idx & 7) * 4;
            uint32_t off = (so + (uint32_t)(r * GTS + c4)) * 4u;
            cpasync16(sbase + off, A + (size_t)(bm + r) * K2 + k0u + c4);
            cpasync16(sbase + off + (uint32_t)GB_OFF_W * 4u, W + (size_t)(bn + r) * K2 + k0u + c4);
        }
        asm volatile("cp.async.commit_group;" ::: "memory");
    }

    __device__ __forceinline__ void run(float acc[4][4][4], int wm, int wn, int lane) {
        // ldmatrix per-lane base addresses (within stage 0)
        const uint32_t a_base = sbase +
            (uint32_t)(((wm + (lane & 7) + ((lane >> 3) & 1) * 8) * GTS + ((lane >> 4) & 1) * 4) * 4);
        const uint32_t b_base = sbase + (uint32_t)GB_OFF_W * 4u +
            (uint32_t)(((wn + (lane & 7) + ((lane >> 4) & 1) * 8) * GTS + ((lane >> 3) & 1) * 4) * 4);

        const int NT = K2 >> 5;
        issue(0, 0);
        issue(1, 1);
        for (int kt = 0; kt < NT; kt++) {
            if (kt < NT - 1) {
                asm volatile("cp.async.wait_group %0;" :: "n"(1) : "memory");
            } else {
                asm volatile("cp.async.wait_group %0;" :: "n"(0) : "memory");
            }
            __syncthreads();
            if (kt + 2 < NT) issue(kt + 2, (kt + 2) % 3);
            const uint32_t so = (uint32_t)((kt % 3) * GSTAGE_W) * 4u;
#pragma unroll
            for (int kk = 0; kk < 4; kk++) {
                const uint32_t ko = (uint32_t)(kk * 8) * 4u;
                uint32_t af[4][4];
#pragma unroll
                for (int mi = 0; mi < 4; mi++)
                    LDSM4(af[mi][0], af[mi][1], af[mi][2], af[mi][3],
                          a_base + so + ko + (uint32_t)(mi * 16 * GTS) * 4u);
                uint32_t bf[4][2];
#pragma unroll
                for (int p = 0; p < 2; p++)
                    LDSM4(bf[2*p][0], bf[2*p][1], bf[2*p+1][0], bf[2*p+1][1],
                          b_base + so + ko + (uint32_t)(p * 16 * GTS) * 4u);
#pragma unroll
                for (int mi = 0; mi < 4; mi++)
#pragma unroll
                    for (int ni = 0; ni < 4; ni++)
                        mma_f16(acc[mi][ni], af[mi], bf[ni]);
            }
        }
    }
};

// Fused QKV projection; q/k written fp16 row-major, v written fp16 TRANSPOSED.
__global__ __launch_bounds__(256, 2) void gemm_qkv(
    const uint32_t* __restrict__ A, const uint32_t* __restrict__ Wc,
    const float* __restrict__ bq, const float* __restrict__ bk, const float* __restrict__ bv,
    uint32_t* __restrict__ q, uint32_t* __restrict__ k, __half* __restrict__ vt)
{
    extern __shared__ uint32_t sh[];
    const int tid = threadIdx.x;
    const int wid = tid >> 5;
    const int lane = tid & 31;
    const int g = lane >> 2, t = lane & 3;
    const int wm = (wid & 1) * 64, wn = (wid >> 1) * 32;
    const int bm = blockIdx.y * 128, bn = blockIdx.x * 128;

    GemmCore core{smem_u32(sh), A, Wc, HIDDEN / 2, bm, bn, tid};
    float acc[4][4][4] = {};
    core.run(acc, wm, wn, lane);

    if (bn < HIDDEN) {
        const float* bias = bq;
#pragma unroll
        for (int mi = 0; mi < 4; mi++)
#pragma unroll
            for (int ni = 0; ni < 4; ni++) {
                const int col = bn + wn + ni * 8 + 2 * t;
                const float bx = __ldg(bias + col);
                const float by = __ldg(bias + col + 1);
                const int rr0 = bm + wm + mi * 16 + g;
                __half2 h0 = __floats2half2_rn(acc[mi][ni][0] + bx, acc[mi][ni][1] + by);
                __half2 h1 = __floats2half2_rn(acc[mi][ni][2] + bx, acc[mi][ni][3] + by);
                q[(size_t)rr0 * (HIDDEN / 2) + (col >> 1)] = *(uint32_t*)&h0;
                q[(size_t)(rr0 + 8) * (HIDDEN / 2) + (col >> 1)] = *(uint32_t*)&h1;
            }
    } else if (bn < HIDDEN + KVDIM) {
        const float* bias = bk;
        const int cb = bn - HIDDEN;
#pragma unroll
        for (int mi = 0; mi < 4; mi++)
#pragma unroll
            for (int ni = 0; ni < 4; ni++) {
                const int col = cb + wn + ni * 8 + 2 * t;
                const float bx = __ldg(bias + col);
                const float by = __ldg(bias + col + 1);
                const int rr0 = bm + wm + mi * 16 + g;
                __half2 h0 = __floats2half2_rn(acc[mi][ni][0] + bx, acc[mi][ni][1] + by);
                __half2 h1 = __floats2half2_rn(acc[mi][ni][2] + bx, acc[mi][ni][3] + by);
                k[(size_t)rr0 * (KVDIM / 2) + (col >> 1)] = *(uint32_t*)&h0;
                k[(size_t)(rr0 + 8) * (KVDIM / 2) + (col >> 1)] = *(uint32_t*)&h1;
            }
    } else {
        const float* bias = bv;
        const int cb = bn - HIDDEN - KVDIM;
#pragma unroll
        for (int mi = 0; mi < 4; mi++)
#pragma unroll
            for (int ni = 0; ni < 4; ni++) {
                const int col = cb + wn + ni * 8 + 2 * t;   // d index (even)
                const float bx = __ldg(bias + col);
                const float by = __ldg(bias + col + 1);
#pragma unroll
                for (int rr = 0; rr < 2; rr++) {
                    const int row = bm + wm + mi * 16 + g + rr * 8;
                    const int bb = row >> 11;
                    const int s  = row & 2047;
                    const float v0 = acc[mi][ni][rr * 2 + 0] + bx;
                    const float v1 = acc[mi][ni][rr * 2 + 1] + by;
                    const size_t base = ((size_t)(bb * NKV + (col >> 6)) * HDIM);
                    vt[(base + (col & 63)) * SEQ + s]     = __float2half_rn(v0);
                    vt[(base + (col & 63) + 1) * SEQ + s] = __float2half_rn(v1);
                }
            }
    }
}

// O-projection: fp16 inputs, fp32 output + bias.
__global__ __launch_bounds__(256, 2) void gemm_oproj(
    const uint32_t* __restrict__ A, const uint32_t* __restrict__ W,
    const float* __restrict__ bias, float* __restrict__ C)
{
    extern __shared__ uint32_t sh[];
    const int tid = threadIdx.x;
    const int wid = tid >> 5;
    const int lane = tid & 31;
    const int g = lane >> 2, t = lane & 3;
    const int wm = (wid & 1) * 64, wn = (wid >> 1) * 32;
    const int bm = blockIdx.y * 128, bn = blockIdx.x * 128;

    GemmCore core{smem_u32(sh), A, W, HIDDEN / 2, bm, bn, tid};
    float acc[4][4][4] = {};
    core.run(acc, wm, wn, lane);

#pragma unroll
    for (int mi = 0; mi < 4; mi++)
#pragma unroll
        for (int ni = 0; ni < 4; ni++) {
            const int col = bn + wn + ni * 8 + 2 * t;
            const float bx = __ldg(bias + col);
            const float by = __ldg(bias + col + 1);
            const int rr0 = bm + wm + mi * 16 + g;
            float2 v0, v1;
            v0.x = acc[mi][ni][0] + bx; v0.y = acc[mi][ni][1] + by;
            v1.x = acc[mi][ni][2] + bx; v1.y = acc[mi][ni][3] + by;
            *(float2*)(C + (size_t)rr0 * HIDDEN + col) = v0;
            *(float2*)(C + (size_t)(rr0 + 8) * HIDDEN + col) = v1;
        }
}

// ---------------------------------------------------------------------------
// fp16 flash attention: register-resident P, ldmatrix K/V fragments,
// double-buffered cp.async K/Vt tiles. (Validated R11.)
// SMEM (uint32): Qs 128x36 | Ks 2x64x36 | Vt 2x64x36 = 55296 B -> 2 CTAs/SM.
// ---------------------------------------------------------------------------
#define ASM_BYTES ((128 * 36 + 2 * 64 * 36 + 2 * 64 * 36) * 4)

__global__ __launch_bounds__(256, 2) void attn_mma(
    const uint32_t* __restrict__ Qh, const uint32_t* __restrict__ Kh,
    const uint32_t* __restrict__ Vth, uint32_t* __restrict__ Oh)
{
    extern __shared__ uint32_t sm32[];
    uint32_t* Qs = sm32;                     // [128][36] (staging only)
    const uint32_t sbase = smem_u32(sm32);
    const uint32_t ks_off = (uint32_t)(128 * 36) * 4u;
    const uint32_t vt_off = ks_off + 2u * 64u * 36u * 4u;

    const int tid = threadIdx.x;
    const int wid = tid >> 5;
    const int lane = tid & 31;
    const int g = lane >> 2;
    const int t = lane & 3;
    const int qb = blockIdx.x;
    const int h  = blockIdx.y;
    const int b  = blockIdx.z;
    const int kvh = h >> 2;

    const uint32_t* Kbase  = Kh + (size_t)(b * SEQ) * (KVDIM / 2) + kvh * (HDIM / 2);
    const uint32_t* Vtbase = Vth + (size_t)((b * NKV + kvh) * HDIM) * (SEQ / 2);

    const uint32_t bl_off =
        (uint32_t)((((lane & 7) + ((lane >> 4) & 1) * 8) * 36 + ((lane >> 3) & 1) * 4) * 4);

    auto issue = [&](int jb, int s) {
#pragma unroll
        for (int j = 0; j < 2; j++) {
            int idx = j * 256 + tid;
            int r = idx >> 3, c4 = (idx & 7) * 4;
            uint32_t so = (uint32_t)(s * 64 * 36 + r * 36 + c4) * 4u;
            cpasync16(sbase + ks_off + so, Kbase + (size_t)(jb * 64 + r) * (KVDIM / 2) + c4);
            cpasync16(sbase + vt_off + so, Vtbase + (size_t)r * (SEQ / 2) + jb * 32 + c4);
        }
        asm volatile("cp.async.commit_group;" ::: "memory");
    };

    issue(0, 0);

    // Stage Q tile (coalesced), scale by 1/8
    {
        const __half2 sc = __float2half2_rn(0.125f);
        const uint32_t* src = Qh + (size_t)(b * SEQ + qb * 128) * (HIDDEN / 2) + h * (HDIM / 2);
#pragma unroll
        for (int j = 0; j < 4; j++) {
            int idx = j * 256 + tid;
            int r = idx >> 3, c = (idx & 7) * 4;
            uint4 v = *(const uint4*)(src + (size_t)r * (HIDDEN / 2) + c);
            __half2* hp = (__half2*)&v;
            hp[0] = __hmul2(hp[0], sc); hp[1] = __hmul2(hp[1], sc);
            hp[2] = __hmul2(hp[2], sc); hp[3] = __hmul2(hp[3], sc);
            uint32_t* dst = &Qs[r * 36 + c];
            dst[0] = v.x; dst[1] = v.y; dst[2] = v.z; dst[3] = v.w;
        }
    }
    __syncthreads();

    const int qr = wid * 16 + g;
    uint32_t qf[4][4];
#pragma unroll
    for (int kk = 0; kk < 4; kk++) {
        const int kc = kk * 8 + t;
        qf[kk][0] = Qs[qr * 36 + kc];
        qf[kk][1] = Qs[(qr + 8) * 36 + kc];
        qf[kk][2] = Qs[qr * 36 + kc + 4];
        qf[kk][3] = Qs[(qr + 8) * 36 + kc + 4];
    }

    float acc_o[8][4] = {};
    float m0 = -1e30f, m1 = -1e30f, l0 = 0.f, l1 = 0.f;

    for (int jb = 0; jb < SEQ / 64; jb++) {
        const int s = jb & 1;
        if (jb + 1 < SEQ / 64) {
            issue(jb + 1, s ^ 1);
            asm volatile("cp.async.wait_group %0;" :: "n"(1) : "memory");
        } else {
            asm volatile("cp.async.wait_group %0;" :: "n"(0) : "memory");
        }
        __syncthreads();

        const uint32_t kf_base = sbase + ks_off + (uint32_t)(s * 64 * 36) * 4u + bl_off;
        const uint32_t vf_base = sbase + vt_off + (uint32_t)(s * 64 * 36) * 4u + bl_off;

        // S = Q K^T
        float acc_s[8][4] = {};
#pragma unroll
        for (int kk = 0; kk < 4; kk++) {
            const uint32_t ko = (uint32_t)(kk * 8) * 4u;
#pragma unroll
            for (int p = 0; p < 4; p++) {
                uint32_t bf[4];
                LDSM4(bf[0], bf[1], bf[2], bf[3], kf_base + ko + (uint32_t)(p * 16 * 36) * 4u);
                mma_f16(acc_s[2*p],     qf[kk], bf);
                mma_f16(acc_s[2*p + 1], qf[kk], bf + 2);
            }
        }

        // Fragment online softmax
        float mx0 = -1e30f, mx1 = -1e30f;
#pragma unroll
        for (int ni = 0; ni < 8; ni++) {
            mx0 = fmaxf(mx0, fmaxf(acc_s[ni][0], acc_s[ni][1]));
            mx1 = fmaxf(mx1, fmaxf(acc_s[ni][2], acc_s[ni][3]));
        }
        mx0 = fmaxf(mx0, __shfl_xor_sync(0xffffffffu, mx0, 1));
        mx0 = fmaxf(mx0, __shfl_xor_sync(0xffffffffu, mx0, 2));
        mx1 = fmaxf(mx1, __shfl_xor_sync(0xffffffffu, mx1, 1));
        mx1 = fmaxf(mx1, __shfl_xor_sync(0xffffffffu, mx1, 2));
        const float mn0 = fmaxf(m0, mx0);
        const float mn1 = fmaxf(m1, mx1);
        const float sf0 = __expf(m0 - mn0);
        const float sf1 = __expf(m1 - mn1);
        m0 = mn0; m1 = mn1;

#pragma unroll
        for (int dn = 0; dn < 8; dn++) {
            acc_o[dn][0] *= sf0; acc_o[dn][1] *= sf0;
            acc_o[dn][2] *= sf1; acc_o[dn][3] *= sf1;
        }

        // P = exp(S - m): pack directly into PV A-fragments
        uint32_t pf[4][4];
        float rs0 = 0.f, rs1 = 0.f;
#pragma unroll
        for (int kb = 0; kb < 4; kb++) {
#pragma unroll
            for (int half = 0; half < 2; half++) {
                const int ni = 2 * kb + half;
                float p0 = __expf(acc_s[ni][0] - mn0);
                float p1 = __expf(acc_s[ni][1] - mn0);
                float p2 = __expf(acc_s[ni][2] - mn1);
                float p3 = __expf(acc_s[ni][3] - mn1);
                rs0 += p0 + p1;
                rs1 += p2 + p3;
                __half2 w0 = __floats2half2_rn(p0, p1);
                __half2 w1 = __floats2half2_rn(p2, p3);
                pf[kb][half * 2 + 0] = *(uint32_t*)&w0;
                pf[kb][half * 2 + 1] = *(uint32_t*)&w1;
            }
        }
        rs0 += __shfl_xor_sync(0xffffffffu, rs0, 1);
        rs0 += __shfl_xor_sync(0xffffffffu, rs0, 2);
        rs1 += __shfl_xor_sync(0xffffffffu, rs1, 1);
        rs1 += __shfl_xor_sync(0xffffffffu, rs1, 2);
        l0 = l0 * sf0 + rs0;
        l1 = l1 * sf1 + rs1;

        // O += P V
#pragma unroll
        for (int kb = 0; kb < 4; kb++) {
            const uint32_t ko = (uint32_t)(kb * 8) * 4u;
#pragma unroll
            for (int p = 0; p < 4; p++) {
                uint32_t bf[4];
                LDSM4(bf[0], bf[1], bf[2], bf[3], vf_base + ko + (uint32_t)(p * 16 * 36) * 4u);
                mma_f16(acc_o[2*p],     pf[kb], bf);
                mma_f16(acc_o[2*p + 1], pf[kb], bf + 2);
            }
        }
        __syncthreads();
    }

    // Epilogue: normalize, store fp16 (feeds O-proj mma)
    const float i0 = 1.f / l0;
    const float i1 = 1.f / l1;
    const int row0 = b * SEQ + qb * 128 + qr;
#pragma unroll
    for (int dn = 0; dn < 8; dn++) {
        const int cp = h * (HDIM / 2) + dn * 4 + t;
        __half2 h0 = __floats2half2_rn(acc_o[dn][0] * i0, acc_o[dn][1] * i0);
        __half2 h1 = __floats2half2_rn(acc_o[dn][2] * i1, acc_o[dn][3] * i1);
        Oh[(size_t)row0 * (HIDDEN / 2) + cp] = *(uint32_t*)&h0;
        Oh[(size_t)(row0 + 8) * (HIDDEN / 2) + cp] = *(uint32_t*)&h1;
    }
}

// ---------------------------------------------------------------------------
extern "C" void kernel_launch(void* const* d_in, const int* in_sizes, int n_in,
                              void* d_out, int out_size)
{
    const float* x  = (const float*)d_in[0];
    const float* wq = (const float*)d_in[1];
    const float* bq = (const float*)d_in[2];
    const float* wk = (const float*)d_in[3];
    const float* bk = (const float*)d_in[4];
    const float* wv = (const float*)d_in[5];
    const float* bv = (const float*)d_in[6];
    const float* wo = (const float*)d_in[7];
    const float* bo = (const float*)d_in[8];
    float* out = (float*)d_out;

    __half *xh, *wqkvh, *woh, *qh, *kh, *vt, *oh;
    cudaGetSymbolAddress((void**)&xh, g_xh);
    cudaGetSymbolAddress((void**)&wqkvh, g_wqkvh);
    cudaGetSymbolAddress((void**)&woh, g_woh);
    cudaGetSymbolAddress((void**)&qh, g_qh);
    cudaGetSymbolAddress((void**)&kh, g_kh);
    cudaGetSymbolAddress((void**)&vt, g_vt);
    cudaGetSymbolAddress((void**)&oh, g_oh);

    cudaFuncSetAttribute(gemm_qkv,   cudaFuncAttributeMaxDynamicSharedMemorySize, GSM_BYTES);
    cudaFuncSetAttribute(gemm_oproj, cudaFuncAttributeMaxDynamicSharedMemorySize, GSM_BYTES);
    cudaFuncSetAttribute(attn_mma,   cudaFuncAttributeMaxDynamicSharedMemorySize, ASM_BYTES);

    cvt_all<<<(TOT4 + 255) / 256, 256>>>(
        (const float4*)x, (const float4*)wq, (const float4*)wk,
        (const float4*)wv, (const float4*)wo,
        (uint2*)xh, (uint2*)wqkvh, (uint2*)woh);

    gemm_qkv<<<dim3(NQKV / 128, MROWS / 128), 256, GSM_BYTES>>>(
        (const uint32_t*)xh, (const uint32_t*)wqkvh, bq, bk, bv,
        (uint32_t*)qh, (uint32_t*)kh, vt);

    attn_mma<<<dim3(SEQ / 128, NHEADS, BATCH), 256, ASM_BYTES>>>(
        (const uint32_t*)qh, (const uint32_t*)kh, (const uint32_t*)vt, (uint32_t*)oh);

    gemm_oproj<<<dim3(HIDDEN / 128, MROWS / 128), 256, GSM_BYTES>>>(
        (const uint32_t*)oh, (const uint32_t*)woh, bo, out);
}